// round 10
// baseline (speedup 1.0000x reference)
#include <cuda_runtime.h>

// B=128, N=32, Do=128, Na=16, H=4, Dk=Dv=64, Dio=144
// out: value [B,N,N,1] (131072) then w [B,H,N,N] (524288), fp32

#define LEAKY(x) ((x) > 0.0f ? (x) : 0.01f * (x))

typedef unsigned long long u64t;

__device__ __forceinline__ u64t bcast2(float x) {
    u64t r; asm("mov.b64 %0, {%1, %1};" : "=l"(r) : "f"(x)); return r;
}
__device__ __forceinline__ u64t fma2(u64t a, u64t b, u64t c) {
    u64t d; asm("fma.rn.f32x2 %0, %1, %2, %3;" : "=l"(d) : "l"(a), "l"(b), "l"(c)); return d;
}
__device__ __forceinline__ float2 unpk(u64t v) {
    float2 f; asm("mov.b64 {%0, %1}, %2;" : "=f"(f.x), "=f"(f.y) : "l"(v)); return f;
}

// ---- shared layout (float offsets) ----
#define OFF_W     0        // 4096
#define OFF_SBD   4096     // 4096   sbd -> rsq
#define OFF_WBUF  8192     // 4096   weight staging (16KB)
#define OFF_STT   12288    // 4224   states^T [d][33]
#define OFF_ACTT  16512    // 528
#define OFF_POLT  17040    // 528
#define OFF_SET   17568    // 4224   se^T [c][33] (later xa^T)
#define OFF_XPT   21792    // 4224   xp^T [c][33]
#define OFF_M1    26016    // 8704   q(68) -> ava(68) -> A(68)
#define OFF_M2    34720    // 8704   k(68) -> avp(68) -> cb(68)
#define OFF_M3    43424    // 8704   cd(68)
#define OFF_SBB   52128    // 128
#define OFF_SDD   52256    // 128
#define OFF_C0    52384    // 64
#define OFF_W2    52448    // 64
#define OFF_CP    52512    // 512
#define OFF_D     8192     // 8704   D(68) overlays WBUF+STT head (dead by P8)
#define SMEM_FLOATS 53024
#define SMEM_BYTES (SMEM_FLOATS * 4)   // 212096 (proven working)

__global__ void __launch_bounds__(1024, 1)
fused_gat_kernel(const float* __restrict__ states,
                 const float* __restrict__ policies,
                 const float* __restrict__ actions,
                 const float* __restrict__ W_se,
                 const float* __restrict__ b_se,
                 const float* __restrict__ W_sape,
                 const float* __restrict__ b_sape,
                 const float* __restrict__ Wk,
                 const float* __restrict__ Wq,
                 const float* __restrict__ Wv,
                 const float* __restrict__ ln_g,
                 const float* __restrict__ ln_b,
                 const float* __restrict__ W_f1,
                 const float* __restrict__ W_f2,
                 float* __restrict__ out_v,
                 float* __restrict__ out_w)
{
    extern __shared__ float sm[];
    const int t = threadIdx.x;
    const int b = blockIdx.x;
    const int lane = t & 31;
    const int wid = t >> 5;      // 0..31

    float* s_w    = sm + OFF_W;
    float* s_sbd  = sm + OFF_SBD;
    float* s_wbuf = sm + OFF_WBUF;
    float* s_stT  = sm + OFF_STT;
    float* s_actT = sm + OFF_ACTT;
    float* s_polT = sm + OFF_POLT;
    float* s_seT  = sm + OFF_SET;   // later xaT
    float* s_xpT  = sm + OFF_XPT;
    float* s_q    = sm + OFF_M1;    // stride 68
    float* s_k    = sm + OFF_M2;    // stride 68
    float* s_ava  = sm + OFF_M1;
    float* s_avp  = sm + OFF_M2;
    float* s_cb   = sm + OFF_M2;
    float* s_cd   = sm + OFF_M3;
    float* s_A    = sm + OFF_M1;
    float* s_D    = sm + OFF_D;
    float* s_sbb  = sm + OFF_SBB;
    float* s_sdd  = sm + OFF_SDD;
    float* s_C0   = sm + OFF_C0;
    float* s_W2   = sm + OFF_W2;
    float* s_cp   = sm + OFF_CP;

    // ---------------- P0: transposed loads + C0 partials ----------------
    {
        #pragma unroll
        for (int o = t; o < 4096; o += 1024) {
            int n = o >> 7, d = o & 127;
            s_stT[d * 33 + n] = states[b * 4096 + o];
        }
        if (t < 512) {
            int n = t >> 4, tt = t & 15;
            s_actT[tt * 33 + n] = actions[b * 512 + t];
            s_polT[tt * 33 + n] = policies[b * 512 + t];
            int m = t & 63, fg = t >> 6;
            float acc = 0.f;
            #pragma unroll 8
            for (int f = fg * 32; f < fg * 32 + 32; f++)
                acc += ln_b[f] * W_f1[f * 64 + m];
            s_cp[fg * 64 + m] = acc;
        }
        if (t < 64) s_W2[t] = W_f2[t];
    }
    __syncthreads();
    if (t < 64) {
        float acc = 0.f;
        #pragma unroll
        for (int g2 = 0; g2 < 8; g2++) acc += s_cp[g2 * 64 + t];
        s_C0[t] = acc;
    }

    // ---------------- P1: se^T = leaky(states @ W_se + b)^T ----------------
    // warp = 4-col group (c0 = wid*4), lane = n
    {
        int c0 = wid * 4;
        ulonglong2 bb = *(const ulonglong2*)(b_se + c0);
        u64t acc0 = bb.x, acc1 = bb.y;
        #pragma unroll 1
        for (int chunk = 0; chunk < 4; chunk++) {
            int d0 = chunk * 32;
            ((float4*)s_wbuf)[t] = ((const float4*)(W_se + d0 * 128))[t];
            __syncthreads();
            #pragma unroll 4
            for (int d = 0; d < 32; d++) {
                u64t a2 = bcast2(s_stT[(d0 + d) * 33 + lane]);
                ulonglong2 w2 = *(const ulonglong2*)(s_wbuf + d * 128 + c0);
                acc0 = fma2(a2, w2.x, acc0);
                acc1 = fma2(a2, w2.y, acc1);
            }
            __syncthreads();
        }
        float2 f0 = unpk(acc0), f1 = unpk(acc1);
        s_seT[(c0 + 0) * 33 + lane] = LEAKY(f0.x);
        s_seT[(c0 + 1) * 33 + lane] = LEAKY(f0.y);
        s_seT[(c0 + 2) * 33 + lane] = LEAKY(f1.x);
        s_seT[(c0 + 3) * 33 + lane] = LEAKY(f1.y);
    }

    // ---------------- P2: q = se @ Wq, then k = se @ Wk ----------------
    // warp = (h = wid>>3, e-group of 8: e0 = (wid&7)*8), lane = n
    {
        int h = wid >> 3, e0 = (wid & 7) * 8;
        int hh = t >> 8, rem = t & 255;
        int sdd2 = rem >> 4, se4 = rem & 15;
        int stage_idx = hh * 2048 + sdd2 * 16 + se4;   // + d0*16
        // ---- q ----
        u64t aq[4] = {0, 0, 0, 0};
        #pragma unroll 1
        for (int chunk = 0; chunk < 8; chunk++) {
            int d0 = chunk * 16;
            ((float4*)s_wbuf)[t] = ((const float4*)Wq)[stage_idx + d0 * 16];
            __syncthreads();
            #pragma unroll 4
            for (int dd = 0; dd < 16; dd++) {
                u64t a2 = bcast2(s_seT[(d0 + dd) * 33 + lane]);
                const ulonglong2* wqr = (const ulonglong2*)(s_wbuf + h * 1024 + dd * 64 + e0);
                ulonglong2 w0 = wqr[0], w1 = wqr[1];
                aq[0] = fma2(a2, w0.x, aq[0]);
                aq[1] = fma2(a2, w0.y, aq[1]);
                aq[2] = fma2(a2, w1.x, aq[2]);
                aq[3] = fma2(a2, w1.y, aq[3]);
            }
            __syncthreads();
        }
        {
            int row = h * 32 + lane;
            float2 q0 = unpk(aq[0]), q1 = unpk(aq[1]), q2 = unpk(aq[2]), q3 = unpk(aq[3]);
            *(float4*)(s_q + row * 68 + e0)     = make_float4(q0.x, q0.y, q1.x, q1.y);
            *(float4*)(s_q + row * 68 + e0 + 4) = make_float4(q2.x, q2.y, q3.x, q3.y);
        }
        // ---- k ----
        u64t ak[4] = {0, 0, 0, 0};
        #pragma unroll 1
        for (int chunk = 0; chunk < 8; chunk++) {
            int d0 = chunk * 16;
            ((float4*)s_wbuf)[t] = ((const float4*)Wk)[stage_idx + d0 * 16];
            __syncthreads();
            #pragma unroll 4
            for (int dd = 0; dd < 16; dd++) {
                u64t a2 = bcast2(s_seT[(d0 + dd) * 33 + lane]);
                const ulonglong2* wkr = (const ulonglong2*)(s_wbuf + h * 1024 + dd * 64 + e0);
                ulonglong2 w0 = wkr[0], w1 = wkr[1];
                ak[0] = fma2(a2, w0.x, ak[0]);
                ak[1] = fma2(a2, w0.y, ak[1]);
                ak[2] = fma2(a2, w1.x, ak[2]);
                ak[3] = fma2(a2, w1.y, ak[3]);
            }
            __syncthreads();
        }
        {
            int row = h * 32 + lane;
            float2 k0 = unpk(ak[0]), k1 = unpk(ak[1]), k2 = unpk(ak[2]), k3 = unpk(ak[3]);
            *(float4*)(s_k + row * 68 + e0)     = make_float4(k0.x, k0.y, k1.x, k1.y);
            *(float4*)(s_k + row * 68 + e0 + 4) = make_float4(k2.x, k2.y, k3.x, k3.y);
        }
    }
    __syncthreads();

    // ---------------- P3: scores ----------------
    {
        int h = t >> 8, rem = t & 255;
        int i = rem >> 3, k2g = rem & 7;
        u64t acc2[4] = {0, 0, 0, 0};
        const float* qr = s_q + (h * 32 + i) * 68;
        const float* kb = s_k + (h * 32 + k2g * 4) * 68;
        #pragma unroll 4
        for (int e0 = 0; e0 < 64; e0 += 4) {
            ulonglong2 q2 = *(const ulonglong2*)(qr + e0);
            #pragma unroll
            for (int kk = 0; kk < 4; kk++) {
                ulonglong2 k2v = *(const ulonglong2*)(kb + kk * 68 + e0);
                acc2[kk] = fma2(q2.x, k2v.x, acc2[kk]);
                acc2[kk] = fma2(q2.y, k2v.y, acc2[kk]);
            }
        }
        #pragma unroll
        for (int kk = 0; kk < 4; kk++) {
            float2 f = unpk(acc2[kk]);
            s_w[h * 1024 + i * 32 + k2g * 4 + kk] = (f.x + f.y) * 0.125f;
        }
    }
    __syncthreads();

    // ---------------- softmax ----------------
    if (t < 128) {
        float* row = s_w + t * 32;
        float mx = row[0];
        #pragma unroll
        for (int j = 1; j < 32; j++) mx = fmaxf(mx, row[j]);
        float s = 0.f;
        #pragma unroll
        for (int j = 0; j < 32; j++) { float ex = __expf(row[j] - mx); row[j] = ex; s += ex; }
        float inv = 1.f / s;
        #pragma unroll
        for (int j = 0; j < 32; j++) row[j] *= inv;
    }
    __syncthreads();
    *(float4*)(out_w + b * 4096 + t * 4) = *(const float4*)(s_w + t * 4);

    // ---------------- P4: xa^T/xp^T ----------------
    {
        int c0 = wid * 4;
        ulonglong2 bb = *(const ulonglong2*)(b_sape + c0);
        u64t bs0 = bb.x, bs1 = bb.y;
        #pragma unroll 1
        for (int chunk = 0; chunk < 4; chunk++) {
            int d0 = chunk * 32;
            ((float4*)s_wbuf)[t] = ((const float4*)(W_sape + d0 * 128))[t];
            __syncthreads();
            #pragma unroll 4
            for (int d = 0; d < 32; d++) {
                u64t a2 = bcast2(s_stT[(d0 + d) * 33 + lane]);
                ulonglong2 w2 = *(const ulonglong2*)(s_wbuf + d * 128 + c0);
                bs0 = fma2(a2, w2.x, bs0);
                bs1 = fma2(a2, w2.y, bs1);
            }
            __syncthreads();
        }
        // tail rows 128..143
        u64t aa0 = bs0, aa1 = bs1, ap0 = bs0, ap1 = bs1;
        if (t < 512) ((float4*)s_wbuf)[t] = ((const float4*)(W_sape + 16384))[t];
        __syncthreads();
        #pragma unroll 4
        for (int tt = 0; tt < 16; tt++) {
            u64t av = bcast2(s_actT[tt * 33 + lane]);
            u64t pv = bcast2(s_polT[tt * 33 + lane]);
            ulonglong2 w2 = *(const ulonglong2*)(s_wbuf + tt * 128 + c0);
            aa0 = fma2(av, w2.x, aa0);
            aa1 = fma2(av, w2.y, aa1);
            ap0 = fma2(pv, w2.x, ap0);
            ap1 = fma2(pv, w2.y, ap1);
        }
        __syncthreads();   // protect WBUF before P5 refill
        float2 fa0 = unpk(aa0), fa1 = unpk(aa1);
        float2 fp0 = unpk(ap0), fp1 = unpk(ap1);
        s_seT[(c0 + 0) * 33 + lane] = LEAKY(fa0.x);   // xaT
        s_seT[(c0 + 1) * 33 + lane] = LEAKY(fa0.y);
        s_seT[(c0 + 2) * 33 + lane] = LEAKY(fa1.x);
        s_seT[(c0 + 3) * 33 + lane] = LEAKY(fa1.y);
        s_xpT[(c0 + 0) * 33 + lane] = LEAKY(fp0.x);
        s_xpT[(c0 + 1) * 33 + lane] = LEAKY(fp0.y);
        s_xpT[(c0 + 2) * 33 + lane] = LEAKY(fp1.x);
        s_xpT[(c0 + 3) * 33 + lane] = LEAKY(fp1.y);
    }

    // ---------------- P5: ava/avp = xa/xp @ Wv ----------------
    {
        int h = wid >> 3, e0 = (wid & 7) * 8;
        int hh = t >> 8, rem = t & 255;
        int stage_idx = hh * 2048 + (rem >> 4) * 16 + (rem & 15);
        u64t aa[4] = {0, 0, 0, 0}, ap[4] = {0, 0, 0, 0};
        #pragma unroll 1
        for (int chunk = 0; chunk < 8; chunk++) {
            int d0 = chunk * 16;
            ((float4*)s_wbuf)[t] = ((const float4*)Wv)[stage_idx + d0 * 16];
            __syncthreads();
            #pragma unroll 4
            for (int dd = 0; dd < 16; dd++) {
                u64t av2 = bcast2(s_seT[(d0 + dd) * 33 + lane]);   // xaT
                u64t pv2 = bcast2(s_xpT[(d0 + dd) * 33 + lane]);
                const ulonglong2* wvr = (const ulonglong2*)(s_wbuf + h * 1024 + dd * 64 + e0);
                ulonglong2 w0 = wvr[0], w1 = wvr[1];
                aa[0] = fma2(av2, w0.x, aa[0]);
                aa[1] = fma2(av2, w0.y, aa[1]);
                aa[2] = fma2(av2, w1.x, aa[2]);
                aa[3] = fma2(av2, w1.y, aa[3]);
                ap[0] = fma2(pv2, w0.x, ap[0]);
                ap[1] = fma2(pv2, w0.y, ap[1]);
                ap[2] = fma2(pv2, w1.x, ap[2]);
                ap[3] = fma2(pv2, w1.y, ap[3]);
            }
            __syncthreads();
        }
        int row = h * 32 + lane;
        float2 a0 = unpk(aa[0]), a1 = unpk(aa[1]), a2f = unpk(aa[2]), a3 = unpk(aa[3]);
        float2 p0 = unpk(ap[0]), p1 = unpk(ap[1]), p2f = unpk(ap[2]), p3 = unpk(ap[3]);
        *(float4*)(s_ava + row * 68 + e0)     = make_float4(a0.x, a0.y, a1.x, a1.y);
        *(float4*)(s_ava + row * 68 + e0 + 4) = make_float4(a2f.x, a2f.y, a3.x, a3.y);
        *(float4*)(s_avp + row * 68 + e0)     = make_float4(p0.x, p0.y, p1.x, p1.y);
        *(float4*)(s_avp + row * 68 + e0 + 4) = make_float4(p2f.x, p2f.y, p3.x, p3.y);
    }
    __syncthreads();

    // ---------------- P6a: cd = avp - ava ----------------
    #pragma unroll
    for (int g = t; g < 2048; g += 1024) {
        int row = g >> 4, e0 = (g & 15) * 4;
        float4 a4 = *(const float4*)(s_ava + row * 68 + e0);
        float4 p4 = *(const float4*)(s_avp + row * 68 + e0);
        *(float4*)(s_cd + row * 68 + e0) =
            make_float4(p4.x - a4.x, p4.y - a4.y, p4.z - a4.z, p4.w - a4.w);
    }
    __syncthreads();

    // ---------------- P6b: cb = w @ ava ----------------
    {
        int h = t >> 8, u = t & 255;
        int i = u >> 3, e0 = (u & 7) * 8;
        u64t acc[4] = {0, 0, 0, 0};
        const float* wrow = s_w + h * 1024 + i * 32;
        const float* av = s_ava + (h * 32) * 68 + e0;
        #pragma unroll 4
        for (int k2 = 0; k2 < 32; k2++) {
            u64t w2 = bcast2(wrow[k2]);
            const ulonglong2* a2 = (const ulonglong2*)(av + k2 * 68);
            ulonglong2 v0 = a2[0], v1 = a2[1];
            acc[0] = fma2(w2, v0.x, acc[0]);
            acc[1] = fma2(w2, v0.y, acc[1]);
            acc[2] = fma2(w2, v1.x, acc[2]);
            acc[3] = fma2(w2, v1.y, acc[3]);
        }
        float* cbr = s_cb + (h * 32 + i) * 68 + e0;
        float2 f0 = unpk(acc[0]), f1 = unpk(acc[1]), f2 = unpk(acc[2]), f3 = unpk(acc[3]);
        *(float4*)(cbr)     = make_float4(f0.x, f0.y, f1.x, f1.y);
        *(float4*)(cbr + 4) = make_float4(f2.x, f2.y, f3.x, f3.y);
    }
    __syncthreads();

    // ---------------- P7a: center rows, sbb/sdd ----------------
    if (t < 256) {
        float* row = ((t < 128) ? s_cb : s_cd) + (t & 127) * 68;
        float acc = 0.f;
        #pragma unroll
        for (int e0 = 0; e0 < 64; e0 += 4) {
            float4 v = *(const float4*)(row + e0);
            acc += v.x + v.y + v.z + v.w;
        }
        float mu = acc * (1.f / 64.f);
        float var = 0.f;
        #pragma unroll
        for (int e0 = 0; e0 < 64; e0 += 4) {
            float4 v = *(const float4*)(row + e0);
            v.x -= mu; v.y -= mu; v.z -= mu; v.w -= mu;
            var += v.x * v.x + v.y * v.y + v.z * v.z + v.w * v.w;
            *(float4*)(row + e0) = v;
        }
        var *= (1.f / 64.f);
        if (t < 128) s_sbb[t] = var; else s_sdd[t & 127] = var;
    }
    __syncthreads();

    // ---------------- P7b: sbd[i,j] ----------------
    {
        int h = t >> 8, u = t & 255;
        int i = u >> 3, jg = u & 7;
        u64t acc2[4] = {0, 0, 0, 0};
        const float* cbr = s_cb + (h * 32 + i) * 68;
        const float* cdr = s_cd + (h * 32 + jg * 4) * 68;
        #pragma unroll 4
        for (int e0 = 0; e0 < 64; e0 += 4) {
            ulonglong2 b2 = *(const ulonglong2*)(cbr + e0);
            #pragma unroll
            for (int jj = 0; jj < 4; jj++) {
                ulonglong2 d2 = *(const ulonglong2*)(cdr + jj * 68 + e0);
                acc2[jj] = fma2(b2.x, d2.x, acc2[jj]);
                acc2[jj] = fma2(b2.y, d2.y, acc2[jj]);
            }
        }
        #pragma unroll
        for (int jj = 0; jj < 4; jj++) {
            float2 f = unpk(acc2[jj]);
            s_sbd[h * 1024 + i * 32 + jg * 4 + jj] = (f.x + f.y) * (1.f / 64.f);
        }
    }
    __syncthreads();

    // ---------------- P7c: scale centered cb/cd by ln_g ----------------
    #pragma unroll
    for (int g = t; g < 2048; g += 1024) {
        int row = g >> 4, e0 = (g & 15) * 4;
        float4 g4 = *(const float4*)(ln_g + (row >> 5) * 64 + e0);
        float4 b4 = *(const float4*)(s_cb + row * 68 + e0);
        float4 d4 = *(const float4*)(s_cd + row * 68 + e0);
        b4.x *= g4.x; b4.y *= g4.y; b4.z *= g4.z; b4.w *= g4.w;
        d4.x *= g4.x; d4.y *= g4.y; d4.z *= g4.z; d4.w *= g4.w;
        *(float4*)(s_cb + row * 68 + e0) = b4;
        *(float4*)(s_cd + row * 68 + e0) = d4;
    }
    __syncthreads();

    // ---------------- P8: A = cb@W1h, D = cd@W1h ----------------
    {
        int h = t >> 8, u = t & 255;
        int m0 = (u & 15) * 4, nr = u >> 4;   // 16 row-slots, rows nr and nr+16
        u64t aA[2][2], aD[2][2];
        #pragma unroll
        for (int r = 0; r < 2; r++) { aA[r][0] = 0; aA[r][1] = 0; aD[r][0] = 0; aD[r][1] = 0; }
        const float* w1b = W_f1 + h * 4096 + m0;
        #pragma unroll 2
        for (int e0 = 0; e0 < 64; e0 += 4) {
            float bvv[2][4], dvv[2][4];
            #pragma unroll
            for (int r = 0; r < 2; r++) {
                int row = h * 32 + nr + 16 * r;
                float4 b4 = *(const float4*)(s_cb + row * 68 + e0);
                float4 d4 = *(const float4*)(s_cd + row * 68 + e0);
                bvv[r][0] = b4.x; bvv[r][1] = b4.y; bvv[r][2] = b4.z; bvv[r][3] = b4.w;
                dvv[r][0] = d4.x; dvv[r][1] = d4.y; dvv[r][2] = d4.z; dvv[r][3] = d4.w;
            }
            #pragma unroll
            for (int ee = 0; ee < 4; ee++) {
                ulonglong2 w2 = *(const ulonglong2*)(w1b + (e0 + ee) * 64);
                #pragma unroll
                for (int r = 0; r < 2; r++) {
                    u64t bv2 = bcast2(bvv[r][ee]);
                    u64t dv2 = bcast2(dvv[r][ee]);
                    aA[r][0] = fma2(bv2, w2.x, aA[r][0]);
                    aA[r][1] = fma2(bv2, w2.y, aA[r][1]);
                    aD[r][0] = fma2(dv2, w2.x, aD[r][0]);
                    aD[r][1] = fma2(dv2, w2.y, aD[r][1]);
                }
            }
        }
        #pragma unroll
        for (int r = 0; r < 2; r++) {
            int row = h * 32 + nr + 16 * r;
            float2 A0 = unpk(aA[r][0]), A1 = unpk(aA[r][1]);
            float2 D0 = unpk(aD[r][0]), D1 = unpk(aD[r][1]);
            *(float4*)(s_A + row * 68 + m0) = make_float4(A0.x, A0.y, A1.x, A1.y);
            *(float4*)(s_D + row * 68 + m0) = make_float4(D0.x, D0.y, D1.x, D1.y);
        }
    }
    __syncthreads();

    // ---------------- P8b: rsq in place of sbd ----------------
    {
        int h = t >> 8, i = (t >> 3) & 31, j0 = (t & 7) * 4;
        int base = h * 1024 + i * 32 + j0;
        float4 w4 = *(const float4*)(s_w + base);
        float4 s4 = *(const float4*)(s_sbd + base);
        float4 dd4 = *(const float4*)(s_sdd + h * 32 + j0);
        float bb = s_sbb[h * 32 + i];
        float4 r;
        r.x = rsqrtf(bb + 2.f * w4.x * s4.x + w4.x * w4.x * dd4.x + 1e-5f);
        r.y = rsqrtf(bb + 2.f * w4.y * s4.y + w4.y * w4.y * dd4.y + 1e-5f);
        r.z = rsqrtf(bb + 2.f * w4.z * s4.z + w4.z * w4.z * dd4.z + 1e-5f);
        r.w = rsqrtf(bb + 2.f * w4.w * s4.w + w4.w * w4.w * dd4.w + 1e-5f);
        *(float4*)(s_sbd + base) = r;
    }
    __syncthreads();

    // ---------------- P9: value (sync-free loop) ----------------
    {
        int j = t >> 5, part = t & 31, m0 = part * 2;   // warp j, lane = m-pair
        u64t C02 = *(const u64t*)(s_C0 + m0);
        float2 W22 = *(const float2*)(s_W2 + m0);
        u64t D2[4];
        #pragma unroll
        for (int h = 0; h < 4; h++)
            D2[h] = *(const u64t*)(s_D + (h * 32 + j) * 68 + m0);
        #pragma unroll 1
        for (int i = 0; i < 32; i++) {
            u64t hid = C02;
            #pragma unroll
            for (int h = 0; h < 4; h++) {
                int idx = h * 1024 + i * 32 + j;
                u64t rq2 = bcast2(s_sbd[idx]);
                u64t wv2 = bcast2(s_w[idx]);
                u64t A2 = *(const u64t*)(s_A + (h * 32 + i) * 68 + m0);
                hid = fma2(rq2, fma2(wv2, D2[h], A2), hid);
            }
            float2 hf = unpk(hid);
            float acc = LEAKY(hf.x) * W22.x + LEAKY(hf.y) * W22.y;
            acc += __shfl_xor_sync(0xffffffffu, acc, 16);
            acc += __shfl_xor_sync(0xffffffffu, acc, 8);
            acc += __shfl_xor_sync(0xffffffffu, acc, 4);
            acc += __shfl_xor_sync(0xffffffffu, acc, 2);
            acc += __shfl_xor_sync(0xffffffffu, acc, 1);
            if (part == 0) out_v[b * 1024 + i * 32 + j] = acc;
        }
    }
}

extern "C" void kernel_launch(void* const* d_in, const int* in_sizes, int n_in,
                              void* d_out, int out_size) {
    const float* states   = (const float*)d_in[0];
    const float* policies = (const float*)d_in[1];
    const float* actions  = (const float*)d_in[2];
    const float* W_se     = (const float*)d_in[3];
    const float* b_se     = (const float*)d_in[4];
    const float* W_sape   = (const float*)d_in[5];
    const float* b_sape   = (const float*)d_in[6];
    const float* Wk       = (const float*)d_in[7];
    const float* Wq       = (const float*)d_in[8];
    const float* Wv       = (const float*)d_in[9];
    const float* ln_g     = (const float*)d_in[10];
    const float* ln_b     = (const float*)d_in[11];
    const float* W_f1     = (const float*)d_in[12];
    const float* W_f2     = (const float*)d_in[13];

    float* out_v = (float*)d_out;                    // [B,N,N,1]
    float* out_w = (float*)d_out + 128 * 32 * 32;    // [B,H,N,N]

    static int configured = 0;
    if (!configured) {
        cudaFuncSetAttribute(fused_gat_kernel,
                             cudaFuncAttributeMaxDynamicSharedMemorySize, SMEM_BYTES);
        configured = 1;
    }

    fused_gat_kernel<<<128, 1024, SMEM_BYTES>>>(states, policies, actions,
                                                W_se, b_se, W_sape, b_sape,
                                                Wk, Wq, Wv, ln_g, ln_b,
                                                W_f1, W_f2, out_v, out_w);
}

// round 11
// speedup vs baseline: 1.1236x; 1.1236x over previous
#include <cuda_runtime.h>

// B=128, N=32, Do=128, Na=16, H=4, Dk=Dv=64, Dio=144
// out: value [B,N,N,1] (131072) then w [B,H,N,N] (524288), fp32

#define LEAKY(x) ((x) > 0.0f ? (x) : 0.01f * (x))

typedef unsigned long long u64t;

__device__ __forceinline__ u64t bcast2(float x) {
    u64t r; asm("mov.b64 %0, {%1, %1};" : "=l"(r) : "f"(x)); return r;
}
__device__ __forceinline__ u64t fma2(u64t a, u64t b, u64t c) {
    u64t d; asm("fma.rn.f32x2 %0, %1, %2, %3;" : "=l"(d) : "l"(a), "l"(b), "l"(c)); return d;
}
__device__ __forceinline__ float2 unpk(u64t v) {
    float2 f; asm("mov.b64 {%0, %1}, %2;" : "=f"(f.x), "=f"(f.y) : "l"(v)); return f;
}

// ---- shared layout (float offsets) ----
#define OFF_W     0        // 4096
#define OFF_SBD   4096     // 4096   sbd -> rsq
#define OFF_WBUF  8192     // 4096   weight staging (16KB)
#define OFF_STT   12288    // 4224   states^T [d][33]
#define OFF_ACTT  16512    // 528
#define OFF_POLT  17040    // 528
#define OFF_SET   17568    // 4224   se^T [c][33] (later xa^T)
#define OFF_XPT   21792    // 4224   xp^T [c][33]
#define OFF_M1    26016    // 8704   q(68) -> ava(68) -> A(68)
#define OFF_M2    34720    // 8704   k(68) -> avp(68) -> cb(68)
#define OFF_M3    43424    // 8704   cd(68)
#define OFF_SBB   52128    // 128
#define OFF_SDD   52256    // 128
#define OFF_C0    52384    // 64
#define OFF_W2    52448    // 64
#define OFF_CP    52512    // 512
#define OFF_D     8192     // 8704   D(68) overlays WBUF+STT head (dead by P8)
#define SMEM_FLOATS 53024
#define SMEM_BYTES (SMEM_FLOATS * 4)   // 212096 (proven working)

__global__ void __launch_bounds__(512, 1)
fused_gat_kernel(const float* __restrict__ states,
                 const float* __restrict__ policies,
                 const float* __restrict__ actions,
                 const float* __restrict__ W_se,
                 const float* __restrict__ b_se,
                 const float* __restrict__ W_sape,
                 const float* __restrict__ b_sape,
                 const float* __restrict__ Wk,
                 const float* __restrict__ Wq,
                 const float* __restrict__ Wv,
                 const float* __restrict__ ln_g,
                 const float* __restrict__ ln_b,
                 const float* __restrict__ W_f1,
                 const float* __restrict__ W_f2,
                 float* __restrict__ out_v,
                 float* __restrict__ out_w)
{
    extern __shared__ float sm[];
    const int t = threadIdx.x;
    const int b = blockIdx.x;
    const int lane = t & 31;
    const int wid = t >> 5;

    float* s_w    = sm + OFF_W;
    float* s_sbd  = sm + OFF_SBD;
    float* s_wbuf = sm + OFF_WBUF;
    float* s_stT  = sm + OFF_STT;
    float* s_actT = sm + OFF_ACTT;
    float* s_polT = sm + OFF_POLT;
    float* s_seT  = sm + OFF_SET;   // later xaT
    float* s_xpT  = sm + OFF_XPT;
    float* s_q    = sm + OFF_M1;    // stride 68
    float* s_k    = sm + OFF_M2;    // stride 68
    float* s_ava  = sm + OFF_M1;
    float* s_avp  = sm + OFF_M2;
    float* s_cb   = sm + OFF_M2;
    float* s_cd   = sm + OFF_M3;
    float* s_A    = sm + OFF_M1;
    float* s_D    = sm + OFF_D;
    float* s_sbb  = sm + OFF_SBB;
    float* s_sdd  = sm + OFF_SDD;
    float* s_C0   = sm + OFF_C0;
    float* s_W2   = sm + OFF_W2;
    float* s_cp   = sm + OFF_CP;

    // ---------------- P0: transposed loads + C0 partials ----------------
    {
        #pragma unroll
        for (int o = t; o < 4096; o += 512) {
            int n = o >> 7, d = o & 127;
            s_stT[d * 33 + n] = states[b * 4096 + o];
        }
        {
            int n = t >> 4, tt = t & 15;
            s_actT[tt * 33 + n] = actions[b * 512 + t];
            s_polT[tt * 33 + n] = policies[b * 512 + t];
        }
        int m = t & 63, fg = t >> 6;
        float acc = 0.f;
        #pragma unroll 8
        for (int f = fg * 32; f < fg * 32 + 32; f++)
            acc += ln_b[f] * W_f1[f * 64 + m];
        s_cp[fg * 64 + m] = acc;
        if (t < 64) s_W2[t] = W_f2[t];
    }
    __syncthreads();
    if (t < 64) {
        float acc = 0.f;
        #pragma unroll
        for (int g2 = 0; g2 < 8; g2++) acc += s_cp[g2 * 64 + t];
        s_C0[t] = acc;
    }

    // ---------------- P1: se^T = leaky(states @ W_se + b)^T ----------------
    // warp = 8-col group, lane = n; register-double-buffered weight staging
    {
        int c0 = wid * 8;
        ulonglong2 bb0 = *(const ulonglong2*)(b_se + c0);
        ulonglong2 bb1 = *(const ulonglong2*)(b_se + c0 + 4);
        u64t acc[4] = {bb0.x, bb0.y, bb1.x, bb1.y};
        float4 pf0 = ((const float4*)W_se)[t];
        float4 pf1 = ((const float4*)W_se)[t + 512];
        #pragma unroll 1
        for (int chunk = 0; chunk < 4; chunk++) {
            ((float4*)s_wbuf)[t] = pf0;
            ((float4*)s_wbuf)[t + 512] = pf1;
            __syncthreads();
            if (chunk < 3) {
                const float4* src = (const float4*)W_se + (chunk + 1) * 1024;
                pf0 = src[t];
                pf1 = src[t + 512];
            }
            int d0 = chunk * 32;
            #pragma unroll 4
            for (int d = 0; d < 32; d++) {
                u64t a2 = bcast2(s_stT[(d0 + d) * 33 + lane]);
                const ulonglong2* wr = (const ulonglong2*)(s_wbuf + d * 128 + c0);
                ulonglong2 w0 = wr[0], w1 = wr[1];
                acc[0] = fma2(a2, w0.x, acc[0]);
                acc[1] = fma2(a2, w0.y, acc[1]);
                acc[2] = fma2(a2, w1.x, acc[2]);
                acc[3] = fma2(a2, w1.y, acc[3]);
            }
            __syncthreads();
        }
        #pragma unroll
        for (int k = 0; k < 4; k++) {
            float2 f = unpk(acc[k]);
            s_seT[(c0 + 2 * k) * 33 + lane]     = LEAKY(f.x);
            s_seT[(c0 + 2 * k + 1) * 33 + lane] = LEAKY(f.y);
        }
    }

    // ---------------- P2: q,k fused = se @ Wq / se @ Wk ----------------
    // 8-d chunks, Wq+Wk co-staged; one act broadcast feeds both.
    // warp = (h = wid>>2, e0 = (wid&3)*16), lane = n
    {
        int h = wid >> 2, e0 = (wid & 3) * 16;
        u64t aq[8], ak[8];
        #pragma unroll
        for (int k = 0; k < 8; k++) { aq[k] = 0; ak[k] = 0; }
        // staging index: float4 idx into W[h][d][e] = hh*2048 + dd*16 + e4
        int hh = t >> 7, rem = t & 127;
        int sidx = hh * 2048 + (rem >> 4) * 16 + (rem & 15);
        float4 pq = ((const float4*)Wq)[sidx];
        float4 pk = ((const float4*)Wk)[sidx];
        #pragma unroll 1
        for (int chunk = 0; chunk < 16; chunk++) {
            ((float4*)s_wbuf)[t] = pq;
            ((float4*)(s_wbuf + 2048))[t] = pk;
            __syncthreads();
            if (chunk < 15) {
                pq = ((const float4*)Wq)[sidx + (chunk + 1) * 128];
                pk = ((const float4*)Wk)[sidx + (chunk + 1) * 128];
            }
            int d0 = chunk * 8;
            #pragma unroll 4
            for (int dd = 0; dd < 8; dd++) {
                u64t a2 = bcast2(s_seT[(d0 + dd) * 33 + lane]);
                const ulonglong2* wqr = (const ulonglong2*)(s_wbuf + h * 512 + dd * 64 + e0);
                const ulonglong2* wkr = (const ulonglong2*)(s_wbuf + 2048 + h * 512 + dd * 64 + e0);
                #pragma unroll
                for (int j = 0; j < 4; j++) {
                    ulonglong2 wq2 = wqr[j];
                    ulonglong2 wk2 = wkr[j];
                    aq[2 * j]     = fma2(a2, wq2.x, aq[2 * j]);
                    aq[2 * j + 1] = fma2(a2, wq2.y, aq[2 * j + 1]);
                    ak[2 * j]     = fma2(a2, wk2.x, ak[2 * j]);
                    ak[2 * j + 1] = fma2(a2, wk2.y, ak[2 * j + 1]);
                }
            }
            __syncthreads();
        }
        int row = h * 32 + lane;
        #pragma unroll
        for (int j = 0; j < 4; j++) {
            float2 q0 = unpk(aq[2 * j]), q1 = unpk(aq[2 * j + 1]);
            float2 k0 = unpk(ak[2 * j]), k1 = unpk(ak[2 * j + 1]);
            *(float4*)(s_q + row * 68 + e0 + j * 4) = make_float4(q0.x, q0.y, q1.x, q1.y);
            *(float4*)(s_k + row * 68 + e0 + j * 4) = make_float4(k0.x, k0.y, k1.x, k1.y);
        }
    }
    __syncthreads();

    // ---------------- P3: scores ----------------
    {
        int h = t >> 7, rem = t & 127;
        int i = rem >> 2, k2g = rem & 3;
        u64t acc2[8] = {0, 0, 0, 0, 0, 0, 0, 0};
        const float* qr = s_q + (h * 32 + i) * 68;
        const float* kb = s_k + (h * 32 + k2g * 8) * 68;
        #pragma unroll 2
        for (int e0 = 0; e0 < 64; e0 += 4) {
            ulonglong2 q2 = *(const ulonglong2*)(qr + e0);
            #pragma unroll
            for (int kk = 0; kk < 8; kk++) {
                ulonglong2 k2v = *(const ulonglong2*)(kb + kk * 68 + e0);
                acc2[kk] = fma2(q2.x, k2v.x, acc2[kk]);
                acc2[kk] = fma2(q2.y, k2v.y, acc2[kk]);
            }
        }
        #pragma unroll
        for (int kk = 0; kk < 8; kk++) {
            float2 f = unpk(acc2[kk]);
            s_w[h * 1024 + i * 32 + k2g * 8 + kk] = (f.x + f.y) * 0.125f;
        }
    }
    __syncthreads();

    // ---------------- softmax ----------------
    if (t < 128) {
        float* row = s_w + t * 32;
        float mx = row[0];
        #pragma unroll
        for (int j = 1; j < 32; j++) mx = fmaxf(mx, row[j]);
        float s = 0.f;
        #pragma unroll
        for (int j = 0; j < 32; j++) { float ex = __expf(row[j] - mx); row[j] = ex; s += ex; }
        float inv = 1.f / s;
        #pragma unroll
        for (int j = 0; j < 32; j++) row[j] *= inv;
    }
    __syncthreads();
    #pragma unroll
    for (int g = t; g < 1024; g += 512)
        *(float4*)(out_w + b * 4096 + g * 4) = *(const float4*)(s_w + g * 4);

    // ---------------- P4: xa^T/xp^T (prefetched staging) ----------------
    {
        int c0 = wid * 8;
        ulonglong2 bb0 = *(const ulonglong2*)(b_sape + c0);
        ulonglong2 bb1 = *(const ulonglong2*)(b_sape + c0 + 4);
        u64t bs[4] = {bb0.x, bb0.y, bb1.x, bb1.y};
        float4 pf0 = ((const float4*)W_sape)[t];
        float4 pf1 = ((const float4*)W_sape)[t + 512];
        float4 pft;
        #pragma unroll 1
        for (int chunk = 0; chunk < 4; chunk++) {
            ((float4*)s_wbuf)[t] = pf0;
            ((float4*)s_wbuf)[t + 512] = pf1;
            __syncthreads();
            if (chunk < 3) {
                const float4* src = (const float4*)W_sape + (chunk + 1) * 1024;
                pf0 = src[t];
                pf1 = src[t + 512];
            } else {
                pft = ((const float4*)W_sape)[4096 + t];   // tail rows 128..143
            }
            int d0 = chunk * 32;
            #pragma unroll 4
            for (int d = 0; d < 32; d++) {
                u64t a2 = bcast2(s_stT[(d0 + d) * 33 + lane]);
                const ulonglong2* wr = (const ulonglong2*)(s_wbuf + d * 128 + c0);
                ulonglong2 w0 = wr[0], w1 = wr[1];
                bs[0] = fma2(a2, w0.x, bs[0]);
                bs[1] = fma2(a2, w0.y, bs[1]);
                bs[2] = fma2(a2, w1.x, bs[2]);
                bs[3] = fma2(a2, w1.y, bs[3]);
            }
            __syncthreads();
        }
        // action/policy tail rows 128..143
        u64t aa[4], ap[4];
        #pragma unroll
        for (int k = 0; k < 4; k++) { aa[k] = bs[k]; ap[k] = bs[k]; }
        ((float4*)s_wbuf)[t] = pft;
        __syncthreads();
        #pragma unroll 4
        for (int tt = 0; tt < 16; tt++) {
            u64t av = bcast2(s_actT[tt * 33 + lane]);
            u64t pv = bcast2(s_polT[tt * 33 + lane]);
            const ulonglong2* wr = (const ulonglong2*)(s_wbuf + tt * 128 + c0);
            ulonglong2 w0 = wr[0], w1 = wr[1];
            aa[0] = fma2(av, w0.x, aa[0]);
            aa[1] = fma2(av, w0.y, aa[1]);
            aa[2] = fma2(av, w1.x, aa[2]);
            aa[3] = fma2(av, w1.y, aa[3]);
            ap[0] = fma2(pv, w0.x, ap[0]);
            ap[1] = fma2(pv, w0.y, ap[1]);
            ap[2] = fma2(pv, w1.x, ap[2]);
            ap[3] = fma2(pv, w1.y, ap[3]);
        }
        __syncthreads();   // protect WBUF before P5 refill
        #pragma unroll
        for (int k = 0; k < 4; k++) {
            float2 fa = unpk(aa[k]), fp = unpk(ap[k]);
            s_seT[(c0 + 2 * k) * 33 + lane]     = LEAKY(fa.x);   // xaT
            s_seT[(c0 + 2 * k + 1) * 33 + lane] = LEAKY(fa.y);
            s_xpT[(c0 + 2 * k) * 33 + lane]     = LEAKY(fp.x);
            s_xpT[(c0 + 2 * k + 1) * 33 + lane] = LEAKY(fp.y);
        }
    }

    // ---------------- P5: ava/avp = xa/xp @ Wv (prefetched staging) --------
    {
        int h = wid >> 2, e0 = (wid & 3) * 16;
        u64t aa[8], ap[8];
        #pragma unroll
        for (int k = 0; k < 8; k++) { aa[k] = 0; ap[k] = 0; }
        int g1 = t + 512;
        int i0 = (t >> 8) * 2048 + ((t & 255) >> 4) * 16 + (t & 15);
        int i1 = (g1 >> 8) * 2048 + ((g1 & 255) >> 4) * 16 + (g1 & 15);
        float4 r0 = ((const float4*)Wv)[i0];
        float4 r1 = ((const float4*)Wv)[i1];
        #pragma unroll 1
        for (int chunk = 0; chunk < 8; chunk++) {
            ((float4*)s_wbuf)[t] = r0;
            ((float4*)s_wbuf)[t + 512] = r1;
            __syncthreads();
            if (chunk < 7) {
                r0 = ((const float4*)Wv)[i0 + (chunk + 1) * 256];
                r1 = ((const float4*)Wv)[i1 + (chunk + 1) * 256];
            }
            int d0 = chunk * 16;
            #pragma unroll 4
            for (int dd = 0; dd < 16; dd++) {
                u64t av2 = bcast2(s_seT[(d0 + dd) * 33 + lane]);   // xaT
                u64t pv2 = bcast2(s_xpT[(d0 + dd) * 33 + lane]);
                const ulonglong2* wvr = (const ulonglong2*)(s_wbuf + h * 1024 + dd * 64 + e0);
                #pragma unroll
                for (int j = 0; j < 4; j++) {
                    ulonglong2 w2 = wvr[j];
                    aa[2 * j]     = fma2(av2, w2.x, aa[2 * j]);
                    aa[2 * j + 1] = fma2(av2, w2.y, aa[2 * j + 1]);
                    ap[2 * j]     = fma2(pv2, w2.x, ap[2 * j]);
                    ap[2 * j + 1] = fma2(pv2, w2.y, ap[2 * j + 1]);
                }
            }
            __syncthreads();
        }
        int row = h * 32 + lane;
        #pragma unroll
        for (int j = 0; j < 4; j++) {
            float2 a0 = unpk(aa[2 * j]), a1 = unpk(aa[2 * j + 1]);
            float2 p0 = unpk(ap[2 * j]), p1 = unpk(ap[2 * j + 1]);
            *(float4*)(s_ava + row * 68 + e0 + j * 4) = make_float4(a0.x, a0.y, a1.x, a1.y);
            *(float4*)(s_avp + row * 68 + e0 + j * 4) = make_float4(p0.x, p0.y, p1.x, p1.y);
        }
    }
    __syncthreads();

    // ---------------- P6a: cd = avp - ava ----------------
    #pragma unroll
    for (int g = t; g < 2048; g += 512) {
        int row = g >> 4, e0 = (g & 15) * 4;
        float4 a4 = *(const float4*)(s_ava + row * 68 + e0);
        float4 p4 = *(const float4*)(s_avp + row * 68 + e0);
        *(float4*)(s_cd + row * 68 + e0) =
            make_float4(p4.x - a4.x, p4.y - a4.y, p4.z - a4.z, p4.w - a4.w);
    }
    __syncthreads();

    // ---------------- P6b: cb = w @ ava ----------------
    {
        int h = t >> 7, u = t & 127;
        int i = u >> 2, e0 = (u & 3) * 16;
        u64t acc[8] = {0, 0, 0, 0, 0, 0, 0, 0};
        const float* wrow = s_w + h * 1024 + i * 32;
        const float* av = s_ava + (h * 32) * 68 + e0;
        #pragma unroll 4
        for (int k2 = 0; k2 < 32; k2++) {
            u64t w2 = bcast2(wrow[k2]);
            const ulonglong2* a2 = (const ulonglong2*)(av + k2 * 68);
            ulonglong2 v0 = a2[0], v1 = a2[1], v2 = a2[2], v3 = a2[3];
            acc[0] = fma2(w2, v0.x, acc[0]);
            acc[1] = fma2(w2, v0.y, acc[1]);
            acc[2] = fma2(w2, v1.x, acc[2]);
            acc[3] = fma2(w2, v1.y, acc[3]);
            acc[4] = fma2(w2, v2.x, acc[4]);
            acc[5] = fma2(w2, v2.y, acc[5]);
            acc[6] = fma2(w2, v3.x, acc[6]);
            acc[7] = fma2(w2, v3.y, acc[7]);
        }
        float* cbr = s_cb + (h * 32 + i) * 68 + e0;
        #pragma unroll
        for (int q4 = 0; q4 < 4; q4++) {
            float2 f0 = unpk(acc[q4 * 2]);
            float2 f1 = unpk(acc[q4 * 2 + 1]);
            *(float4*)(cbr + q4 * 4) = make_float4(f0.x, f0.y, f1.x, f1.y);
        }
    }
    __syncthreads();

    // ---------------- P7a: center rows, sbb/sdd ----------------
    if (t < 256) {
        float* row = ((t < 128) ? s_cb : s_cd) + (t & 127) * 68;
        float acc = 0.f;
        #pragma unroll
        for (int e0 = 0; e0 < 64; e0 += 4) {
            float4 v = *(const float4*)(row + e0);
            acc += v.x + v.y + v.z + v.w;
        }
        float mu = acc * (1.f / 64.f);
        float var = 0.f;
        #pragma unroll
        for (int e0 = 0; e0 < 64; e0 += 4) {
            float4 v = *(const float4*)(row + e0);
            v.x -= mu; v.y -= mu; v.z -= mu; v.w -= mu;
            var += v.x * v.x + v.y * v.y + v.z * v.z + v.w * v.w;
            *(float4*)(row + e0) = v;
        }
        var *= (1.f / 64.f);
        if (t < 128) s_sbb[t] = var; else s_sdd[t & 127] = var;
    }
    __syncthreads();

    // ---------------- P7b: sbd[i,j] ----------------
    {
        int h = t >> 7, u = t & 127;
        int i = u >> 2, jg = u & 3;
        u64t acc2[8] = {0, 0, 0, 0, 0, 0, 0, 0};
        const float* cbr = s_cb + (h * 32 + i) * 68;
        const float* cdr = s_cd + (h * 32 + jg * 8) * 68;
        #pragma unroll 2
        for (int e0 = 0; e0 < 64; e0 += 4) {
            ulonglong2 b2 = *(const ulonglong2*)(cbr + e0);
            #pragma unroll
            for (int jj = 0; jj < 8; jj++) {
                ulonglong2 d2 = *(const ulonglong2*)(cdr + jj * 68 + e0);
                acc2[jj] = fma2(b2.x, d2.x, acc2[jj]);
                acc2[jj] = fma2(b2.y, d2.y, acc2[jj]);
            }
        }
        #pragma unroll
        for (int jj = 0; jj < 8; jj++) {
            float2 f = unpk(acc2[jj]);
            s_sbd[h * 1024 + i * 32 + jg * 8 + jj] = (f.x + f.y) * (1.f / 64.f);
        }
    }
    __syncthreads();

    // ---------------- P7c: scale centered cb/cd by ln_g ----------------
    #pragma unroll
    for (int g = t; g < 2048; g += 512) {
        int row = g >> 4, e0 = (g & 15) * 4;
        float4 g4 = *(const float4*)(ln_g + (row >> 5) * 64 + e0);
        float4 b4 = *(const float4*)(s_cb + row * 68 + e0);
        float4 d4 = *(const float4*)(s_cd + row * 68 + e0);
        b4.x *= g4.x; b4.y *= g4.y; b4.z *= g4.z; b4.w *= g4.w;
        d4.x *= g4.x; d4.y *= g4.y; d4.z *= g4.z; d4.w *= g4.w;
        *(float4*)(s_cb + row * 68 + e0) = b4;
        *(float4*)(s_cd + row * 68 + e0) = d4;
    }
    __syncthreads();

    // ---------------- P8: A = cb@W1h, D = cd@W1h ----------------
    {
        int h = t >> 7, u = t & 127;
        int m0 = (u & 15) * 4, nr = u >> 4;
        u64t aA[4][2], aD[4][2];
        #pragma unroll
        for (int r = 0; r < 4; r++) { aA[r][0] = 0; aA[r][1] = 0; aD[r][0] = 0; aD[r][1] = 0; }
        const float* w1b = W_f1 + h * 4096 + m0;
        #pragma unroll 2
        for (int e0 = 0; e0 < 64; e0 += 4) {
            float bvv[4][4], dvv[4][4];
            #pragma unroll
            for (int r = 0; r < 4; r++) {
                int row = h * 32 + nr + 8 * r;
                float4 b4 = *(const float4*)(s_cb + row * 68 + e0);
                float4 d4 = *(const float4*)(s_cd + row * 68 + e0);
                bvv[r][0] = b4.x; bvv[r][1] = b4.y; bvv[r][2] = b4.z; bvv[r][3] = b4.w;
                dvv[r][0] = d4.x; dvv[r][1] = d4.y; dvv[r][2] = d4.z; dvv[r][3] = d4.w;
            }
            #pragma unroll
            for (int ee = 0; ee < 4; ee++) {
                ulonglong2 w2 = *(const ulonglong2*)(w1b + (e0 + ee) * 64);
                #pragma unroll
                for (int r = 0; r < 4; r++) {
                    u64t bv2 = bcast2(bvv[r][ee]);
                    u64t dv2 = bcast2(dvv[r][ee]);
                    aA[r][0] = fma2(bv2, w2.x, aA[r][0]);
                    aA[r][1] = fma2(bv2, w2.y, aA[r][1]);
                    aD[r][0] = fma2(dv2, w2.x, aD[r][0]);
                    aD[r][1] = fma2(dv2, w2.y, aD[r][1]);
                }
            }
        }
        #pragma unroll
        for (int r = 0; r < 4; r++) {
            int row = h * 32 + nr + 8 * r;
            float2 A0 = unpk(aA[r][0]), A1 = unpk(aA[r][1]);
            float2 D0 = unpk(aD[r][0]), D1 = unpk(aD[r][1]);
            *(float4*)(s_A + row * 68 + m0) = make_float4(A0.x, A0.y, A1.x, A1.y);
            *(float4*)(s_D + row * 68 + m0) = make_float4(D0.x, D0.y, D1.x, D1.y);
        }
    }
    __syncthreads();

    // ---------------- P8b: rsq in place of sbd ----------------
    #pragma unroll
    for (int g = t; g < 1024; g += 512) {
        int h = g >> 8, i = (g >> 3) & 31, j0 = (g & 7) * 4;
        int base = h * 1024 + i * 32 + j0;
        float4 w4 = *(const float4*)(s_w + base);
        float4 s4 = *(const float4*)(s_sbd + base);
        float4 dd4 = *(const float4*)(s_sdd + h * 32 + j0);
        float bb = s_sbb[h * 32 + i];
        float4 r;
        r.x = rsqrtf(bb + 2.f * w4.x * s4.x + w4.x * w4.x * dd4.x + 1e-5f);
        r.y = rsqrtf(bb + 2.f * w4.y * s4.y + w4.y * w4.y * dd4.y + 1e-5f);
        r.z = rsqrtf(bb + 2.f * w4.z * s4.z + w4.z * w4.z * dd4.z + 1e-5f);
        r.w = rsqrtf(bb + 2.f * w4.w * s4.w + w4.w * w4.w * dd4.w + 1e-5f);
        *(float4*)(s_sbd + base) = r;
    }
    __syncthreads();

    // ---------------- P9: value (sync-free loop) ----------------
    {
        int j = t >> 4, part = t & 15, m0 = part * 4;
        ulonglong2 C02 = *(const ulonglong2*)(s_C0 + m0);
        float4 W24 = *(const float4*)(s_W2 + m0);
        u64t D2[4][2];
        #pragma unroll
        for (int h = 0; h < 4; h++) {
            ulonglong2 d2 = *(const ulonglong2*)(s_D + (h * 32 + j) * 68 + m0);
            D2[h][0] = d2.x; D2[h][1] = d2.y;
        }
        #pragma unroll 1
        for (int i = 0; i < 32; i++) {
            u64t hid0 = C02.x, hid1 = C02.y;
            #pragma unroll
            for (int h = 0; h < 4; h++) {
                int idx = h * 1024 + i * 32 + j;
                u64t rq2 = bcast2(s_sbd[idx]);
                u64t wv2 = bcast2(s_w[idx]);
                ulonglong2 A2 = *(const ulonglong2*)(s_A + (h * 32 + i) * 68 + m0);
                u64t t0 = fma2(wv2, D2[h][0], A2.x);
                hid0 = fma2(rq2, t0, hid0);
                u64t t1 = fma2(wv2, D2[h][1], A2.y);
                hid1 = fma2(rq2, t1, hid1);
            }
            float2 h0 = unpk(hid0), h1 = unpk(hid1);
            float acc = LEAKY(h0.x) * W24.x + LEAKY(h0.y) * W24.y
                      + LEAKY(h1.x) * W24.z + LEAKY(h1.y) * W24.w;
            acc += __shfl_xor_sync(0xffffffffu, acc, 8);
            acc += __shfl_xor_sync(0xffffffffu, acc, 4);
            acc += __shfl_xor_sync(0xffffffffu, acc, 2);
            acc += __shfl_xor_sync(0xffffffffu, acc, 1);
            if (part == 0) out_v[b * 1024 + i * 32 + j] = acc;
        }
    }
}

extern "C" void kernel_launch(void* const* d_in, const int* in_sizes, int n_in,
                              void* d_out, int out_size) {
    const float* states   = (const float*)d_in[0];
    const float* policies = (const float*)d_in[1];
    const float* actions  = (const float*)d_in[2];
    const float* W_se     = (const float*)d_in[3];
    const float* b_se     = (const float*)d_in[4];
    const float* W_sape   = (const float*)d_in[5];
    const float* b_sape   = (const float*)d_in[6];
    const float* Wk       = (const float*)d_in[7];
    const float* Wq       = (const float*)d_in[8];
    const float* Wv       = (const float*)d_in[9];
    const float* ln_g     = (const float*)d_in[10];
    const float* ln_b     = (const float*)d_in[11];
    const float* W_f1     = (const float*)d_in[12];
    const float* W_f2     = (const float*)d_in[13];

    float* out_v = (float*)d_out;                    // [B,N,N,1]
    float* out_w = (float*)d_out + 128 * 32 * 32;    // [B,H,N,N]

    static int configured = 0;
    if (!configured) {
        cudaFuncSetAttribute(fused_gat_kernel,
                             cudaFuncAttributeMaxDynamicSharedMemorySize, SMEM_BYTES);
        configured = 1;
    }

    fused_gat_kernel<<<128, 512, SMEM_BYTES>>>(states, policies, actions,
                                               W_se, b_se, W_sape, b_sape,
                                               Wk, Wq, Wv, ln_g, ln_b,
                                               W_f1, W_f2, out_v, out_w);
}

// round 13
// speedup vs baseline: 1.1367x; 1.0116x over previous
#include <cuda_runtime.h>

// B=128, N=32, Do=128, Na=16, H=4, Dk=Dv=64, Dio=144
// out: value [B,N,N,1] (131072) then w [B,H,N,N] (524288), fp32

#define LEAKY(x) ((x) > 0.0f ? (x) : 0.01f * (x))

typedef unsigned long long u64t;

__device__ __forceinline__ u64t bcast2(float x) {
    u64t r; asm("mov.b64 %0, {%1, %1};" : "=l"(r) : "f"(x)); return r;
}
__device__ __forceinline__ u64t fma2(u64t a, u64t b, u64t c) {
    u64t d; asm("fma.rn.f32x2 %0, %1, %2, %3;" : "=l"(d) : "l"(a), "l"(b), "l"(c)); return d;
}
__device__ __forceinline__ float2 unpk(u64t v) {
    float2 f; asm("mov.b64 {%0, %1}, %2;" : "=f"(f.x), "=f"(f.y) : "l"(v)); return f;
}

// ---- shared layout (float offsets) ----
#define OFF_W     0        // 4096   softmax w
#define OFF_SBD   4096     // 4096   sbd -> rsq
#define OFF_WBUF  8192     // 4096   staging buf0
#define OFF_ST    12288    // 4224   states row-major [n][132]
#define OFF_ACT   16512    // 640    [n][20]
#define OFF_POL   17152    // 640
#define OFF_SE    17792    // 4224   se/xa row-major [n][132]
#define OFF_XP    22016    // 4224   xp row-major [n][132]
#define OFF_M1    26240    // 8704   q(68) -> ava(68) -> A(68); CP overlay in P0
#define OFF_M2    34944    // 8704   k(68) -> avp(68) -> cb(68)
#define OFF_M3    43648    // 8704   staging buf1 -> cd(68)
#define OFF_SBB   52352    // 128
#define OFF_SDD   52480    // 128
#define OFF_C0    52608    // 64
#define OFF_W2    52672    // 64
#define OFF_D     8192     // 8704   D(68) overlays WBUF+ST+ACT head (dead by P8)
#define SMEM_FLOATS 52736
#define SMEM_BYTES (SMEM_FLOATS * 4)   // 210944 (< proven 212480)

__global__ void __launch_bounds__(512, 1)
fused_gat_kernel(const float* __restrict__ states,
                 const float* __restrict__ policies,
                 const float* __restrict__ actions,
                 const float* __restrict__ W_se,
                 const float* __restrict__ b_se,
                 const float* __restrict__ W_sape,
                 const float* __restrict__ b_sape,
                 const float* __restrict__ Wk,
                 const float* __restrict__ Wq,
                 const float* __restrict__ Wv,
                 const float* __restrict__ ln_g,
                 const float* __restrict__ ln_b,
                 const float* __restrict__ W_f1,
                 const float* __restrict__ W_f2,
                 float* __restrict__ out_v,
                 float* __restrict__ out_w)
{
    extern __shared__ float sm[];
    const int t = threadIdx.x;
    const int b = blockIdx.x;
    const int lane = t & 31;
    const int wid = t >> 5;

    float* s_w    = sm + OFF_W;
    float* s_sbd  = sm + OFF_SBD;
    float* s_wbuf = sm + OFF_WBUF;
    float* s_m3   = sm + OFF_M3;
    float* s_st   = sm + OFF_ST;
    float* s_act  = sm + OFF_ACT;
    float* s_pol  = sm + OFF_POL;
    float* s_se   = sm + OFF_SE;    // later xa
    float* s_xp   = sm + OFF_XP;
    float* s_q    = sm + OFF_M1;    // stride 68
    float* s_k    = sm + OFF_M2;    // stride 68
    float* s_ava  = sm + OFF_M1;
    float* s_avp  = sm + OFF_M2;
    float* s_cb   = sm + OFF_M2;
    float* s_cd   = sm + OFF_M3;
    float* s_A    = sm + OFF_M1;
    float* s_D    = sm + OFF_D;
    float* s_sbb  = sm + OFF_SBB;
    float* s_sdd  = sm + OFF_SDD;
    float* s_C0   = sm + OFF_C0;
    float* s_W2   = sm + OFF_W2;
    float* s_cp   = sm + OFF_M1;    // CP overlay (P0 only; M1 free then)

    // ---------------- P0: row-major loads + C0 partials ----------------
    {
        #pragma unroll
        for (int o = t; o < 4096; o += 512) {
            int n = o >> 7, d = o & 127;
            s_st[n * 132 + d] = states[b * 4096 + o];
        }
        {
            int n = t >> 4, tt = t & 15;
            s_act[n * 20 + tt] = actions[b * 512 + t];
            s_pol[n * 20 + tt] = policies[b * 512 + t];
        }
        int m = t & 63, fg = t >> 6;
        float acc = 0.f;
        #pragma unroll 8
        for (int f = fg * 32; f < fg * 32 + 32; f++)
            acc += ln_b[f] * W_f1[f * 64 + m];
        s_cp[fg * 64 + m] = acc;
        if (t < 64) s_W2[t] = W_f2[t];
    }
    __syncthreads();
    if (t < 64) {
        float acc = 0.f;
        #pragma unroll
        for (int g2 = 0; g2 < 8; g2++) acc += s_cp[g2 * 64 + t];
        s_C0[t] = acc;
    }

    // ---------------- P1: se = leaky(states @ W_se + b), row-major ------
    // warp = 8-col group, lane = n; single-bar double-buffered staging
    {
        int c0 = wid * 8;
        ulonglong2 bb0 = *(const ulonglong2*)(b_se + c0);
        ulonglong2 bb1 = *(const ulonglong2*)(b_se + c0 + 4);
        u64t acc[4] = {bb0.x, bb0.y, bb1.x, bb1.y};
        const float4* Wse4 = (const float4*)W_se;
        float4 pf0 = Wse4[t], pf1 = Wse4[t + 512];
        ((float4*)s_wbuf)[t] = pf0;
        ((float4*)s_wbuf)[t + 512] = pf1;
        pf0 = Wse4[1024 + t]; pf1 = Wse4[1536 + t];
        __syncthreads();
        #pragma unroll 1
        for (int c = 0; c < 4; c++) {
            float* cur = (c & 1) ? s_m3 : s_wbuf;
            float* nxt = (c & 1) ? s_wbuf : s_m3;
            if (c < 3) {
                ((float4*)nxt)[t] = pf0;
                ((float4*)nxt)[t + 512] = pf1;
                if (c < 2) {
                    pf0 = Wse4[(c + 2) * 1024 + t];
                    pf1 = Wse4[(c + 2) * 1024 + 512 + t];
                }
            }
            int d0 = c * 32;
            #pragma unroll 2
            for (int d4 = 0; d4 < 8; d4++) {
                float4 a4 = *(const float4*)(s_st + lane * 132 + d0 + d4 * 4);
                float av[4] = {a4.x, a4.y, a4.z, a4.w};
                #pragma unroll
                for (int dd = 0; dd < 4; dd++) {
                    u64t a2 = bcast2(av[dd]);
                    const ulonglong2* wr = (const ulonglong2*)(cur + (d4 * 4 + dd) * 128 + c0);
                    ulonglong2 w0 = wr[0], w1 = wr[1];
                    acc[0] = fma2(a2, w0.x, acc[0]);
                    acc[1] = fma2(a2, w0.y, acc[1]);
                    acc[2] = fma2(a2, w1.x, acc[2]);
                    acc[3] = fma2(a2, w1.y, acc[3]);
                }
            }
            __syncthreads();
        }
        #pragma unroll
        for (int k = 0; k < 4; k++) {
            float2 f = unpk(acc[k]);
            s_se[lane * 132 + c0 + 2 * k]     = LEAKY(f.x);
            s_se[lane * 132 + c0 + 2 * k + 1] = LEAKY(f.y);
        }
    }

    // ---------------- P2: q,k = se @ Wq / se @ Wk (fused staging) --------
    // warp = (h = wid>>2, e0 = (wid&3)*16), lane = n; 16 chunks of 8d
    {
        int h = wid >> 2, e0 = (wid & 3) * 16;
        u64t aq[8], ak[8];
        #pragma unroll
        for (int k = 0; k < 8; k++) { aq[k] = 0; ak[k] = 0; }
        int hh = t >> 7, rem = t & 127;
        int sidx = hh * 2048 + (rem >> 4) * 16 + (rem & 15);
        const float4* Wq4 = (const float4*)Wq;
        const float4* Wk4 = (const float4*)Wk;
        float4 pq = Wq4[sidx], pk = Wk4[sidx];
        ((float4*)s_wbuf)[t] = pq;
        ((float4*)s_wbuf)[t + 512] = pk;
        pq = Wq4[sidx + 128]; pk = Wk4[sidx + 128];
        __syncthreads();
        #pragma unroll 1
        for (int c = 0; c < 16; c++) {
            float* cur = (c & 1) ? s_m3 : s_wbuf;
            float* nxt = (c & 1) ? s_wbuf : s_m3;
            if (c < 15) {
                ((float4*)nxt)[t] = pq;
                ((float4*)nxt)[t + 512] = pk;
                if (c < 14) {
                    pq = Wq4[sidx + (c + 2) * 128];
                    pk = Wk4[sidx + (c + 2) * 128];
                }
            }
            int d0 = c * 8;
            #pragma unroll
            for (int d4 = 0; d4 < 2; d4++) {
                float4 a4 = *(const float4*)(s_se + lane * 132 + d0 + d4 * 4);
                float av[4] = {a4.x, a4.y, a4.z, a4.w};
                #pragma unroll
                for (int dd = 0; dd < 4; dd++) {
                    u64t a2 = bcast2(av[dd]);
                    int dl = d4 * 4 + dd;
                    const ulonglong2* wqr = (const ulonglong2*)(cur + h * 512 + dl * 64 + e0);
                    const ulonglong2* wkr = (const ulonglong2*)(cur + 2048 + h * 512 + dl * 64 + e0);
                    #pragma unroll
                    for (int j = 0; j < 4; j++) {
                        ulonglong2 wq2 = wqr[j];
                        ulonglong2 wk2 = wkr[j];
                        aq[2 * j]     = fma2(a2, wq2.x, aq[2 * j]);
                        aq[2 * j + 1] = fma2(a2, wq2.y, aq[2 * j + 1]);
                        ak[2 * j]     = fma2(a2, wk2.x, ak[2 * j]);
                        ak[2 * j + 1] = fma2(a2, wk2.y, ak[2 * j + 1]);
                    }
                }
            }
            __syncthreads();
        }
        int row = h * 32 + lane;
        #pragma unroll
        for (int j = 0; j < 4; j++) {
            float2 q0 = unpk(aq[2 * j]), q1 = unpk(aq[2 * j + 1]);
            float2 k0 = unpk(ak[2 * j]), k1 = unpk(ak[2 * j + 1]);
            *(float4*)(s_q + row * 68 + e0 + j * 4) = make_float4(q0.x, q0.y, q1.x, q1.y);
            *(float4*)(s_k + row * 68 + e0 + j * 4) = make_float4(k0.x, k0.y, k1.x, k1.y);
        }
    }
    __syncthreads();

    // ---------------- P3: scores ----------------
    {
        int h = t >> 7, rem = t & 127;
        int i = rem >> 2, k2g = rem & 3;
        u64t acc2[8] = {0, 0, 0, 0, 0, 0, 0, 0};
        const float* qr = s_q + (h * 32 + i) * 68;
        const float* kb = s_k + (h * 32 + k2g * 8) * 68;
        #pragma unroll 2
        for (int e0 = 0; e0 < 64; e0 += 4) {
            ulonglong2 q2 = *(const ulonglong2*)(qr + e0);
            #pragma unroll
            for (int kk = 0; kk < 8; kk++) {
                ulonglong2 k2v = *(const ulonglong2*)(kb + kk * 68 + e0);
                acc2[kk] = fma2(q2.x, k2v.x, acc2[kk]);
                acc2[kk] = fma2(q2.y, k2v.y, acc2[kk]);
            }
        }
        #pragma unroll
        for (int kk = 0; kk < 8; kk++) {
            float2 f = unpk(acc2[kk]);
            s_w[h * 1024 + i * 32 + k2g * 8 + kk] = (f.x + f.y) * 0.125f;
        }
    }
    __syncthreads();

    // ---------------- softmax ----------------
    if (t < 128) {
        float* row = s_w + t * 32;
        float mx = row[0];
        #pragma unroll
        for (int j = 1; j < 32; j++) mx = fmaxf(mx, row[j]);
        float s = 0.f;
        #pragma unroll
        for (int j = 0; j < 32; j++) { float ex = __expf(row[j] - mx); row[j] = ex; s += ex; }
        float inv = 1.f / s;
        #pragma unroll
        for (int j = 0; j < 32; j++) row[j] *= inv;
    }
    __syncthreads();
    #pragma unroll
    for (int g = t; g < 1024; g += 512)
        *(float4*)(out_w + b * 4096 + g * 4) = *(const float4*)(s_w + g * 4);

    // ---------------- P4: xa/xp row-major (staged + tail) ----------------
    {
        int c0 = wid * 8;
        ulonglong2 bb0 = *(const ulonglong2*)(b_sape + c0);
        ulonglong2 bb1 = *(const ulonglong2*)(b_sape + c0 + 4);
        u64t bs[4] = {bb0.x, bb0.y, bb1.x, bb1.y};
        const float4* Ws4 = (const float4*)W_sape;
        float4 pf0 = Ws4[t], pf1 = Ws4[t + 512];
        float4 pft;
        ((float4*)s_wbuf)[t] = pf0;
        ((float4*)s_wbuf)[t + 512] = pf1;
        pf0 = Ws4[1024 + t]; pf1 = Ws4[1536 + t];
        __syncthreads();
        #pragma unroll 1
        for (int c = 0; c < 4; c++) {
            float* cur = (c & 1) ? s_m3 : s_wbuf;
            float* nxt = (c & 1) ? s_wbuf : s_m3;
            if (c < 3) {
                ((float4*)nxt)[t] = pf0;
                ((float4*)nxt)[t + 512] = pf1;
                if (c < 2) {
                    pf0 = Ws4[(c + 2) * 1024 + t];
                    pf1 = Ws4[(c + 2) * 1024 + 512 + t];
                } else {
                    pft = Ws4[4096 + t];   // tail rows 128..143
                }
            } else {
                ((float4*)nxt)[t] = pft;   // c==3: nxt = WBUF
            }
            int d0 = c * 32;
            #pragma unroll 2
            for (int d4 = 0; d4 < 8; d4++) {
                float4 a4 = *(const float4*)(s_st + lane * 132 + d0 + d4 * 4);
                float av[4] = {a4.x, a4.y, a4.z, a4.w};
                #pragma unroll
                for (int dd = 0; dd < 4; dd++) {
                    u64t a2 = bcast2(av[dd]);
                    const ulonglong2* wr = (const ulonglong2*)(cur + (d4 * 4 + dd) * 128 + c0);
                    ulonglong2 w0 = wr[0], w1 = wr[1];
                    bs[0] = fma2(a2, w0.x, bs[0]);
                    bs[1] = fma2(a2, w0.y, bs[1]);
                    bs[2] = fma2(a2, w1.x, bs[2]);
                    bs[3] = fma2(a2, w1.y, bs[3]);
                }
            }
            __syncthreads();
        }
        // tail: action/policy rows, weights staged in WBUF
        u64t aa[4], ap[4];
        #pragma unroll
        for (int k = 0; k < 4; k++) { aa[k] = bs[k]; ap[k] = bs[k]; }
        #pragma unroll
        for (int t4 = 0; t4 < 4; t4++) {
            float4 sa4 = *(const float4*)(s_act + lane * 20 + t4 * 4);
            float4 sp4 = *(const float4*)(s_pol + lane * 20 + t4 * 4);
            float sav[4] = {sa4.x, sa4.y, sa4.z, sa4.w};
            float spv[4] = {sp4.x, sp4.y, sp4.z, sp4.w};
            #pragma unroll
            for (int dd = 0; dd < 4; dd++) {
                int tt = t4 * 4 + dd;
                u64t av = bcast2(sav[dd]);
                u64t pv = bcast2(spv[dd]);
                const ulonglong2* wr = (const ulonglong2*)(s_wbuf + tt * 128 + c0);
                ulonglong2 w0 = wr[0], w1 = wr[1];
                aa[0] = fma2(av, w0.x, aa[0]);
                aa[1] = fma2(av, w0.y, aa[1]);
                aa[2] = fma2(av, w1.x, aa[2]);
                aa[3] = fma2(av, w1.y, aa[3]);
                ap[0] = fma2(pv, w0.x, ap[0]);
                ap[1] = fma2(pv, w0.y, ap[1]);
                ap[2] = fma2(pv, w1.x, ap[2]);
                ap[3] = fma2(pv, w1.y, ap[3]);
            }
        }
        #pragma unroll
        for (int k = 0; k < 4; k++) {
            float2 fa = unpk(aa[k]), fp = unpk(ap[k]);
            s_se[lane * 132 + c0 + 2 * k]     = LEAKY(fa.x);   // xa
            s_se[lane * 132 + c0 + 2 * k + 1] = LEAKY(fa.y);
            s_xp[lane * 132 + c0 + 2 * k]     = LEAKY(fp.x);
            s_xp[lane * 132 + c0 + 2 * k + 1] = LEAKY(fp.y);
        }
    }
    __syncthreads();   // xa/xp visible; WBUF reads done before P5 staging

    // ---------------- P5: ava/avp = xa/xp @ Wv (8 chunks of 16d) ---------
    {
        int h = wid >> 2, e0 = (wid & 3) * 16;
        u64t aa[8], ap[8];
        #pragma unroll
        for (int k = 0; k < 8; k++) { aa[k] = 0; ap[k] = 0; }
        int g1 = t + 512;
        int i0 = (t >> 8) * 2048 + ((t & 255) >> 4) * 16 + (t & 15);
        int i1 = (g1 >> 8) * 2048 + ((g1 & 255) >> 4) * 16 + (g1 & 15);
        const float4* Wv4 = (const float4*)Wv;
        float4 r0 = Wv4[i0], r1 = Wv4[i1];
        ((float4*)s_wbuf)[t] = r0;
        ((float4*)s_wbuf)[t + 512] = r1;
        r0 = Wv4[i0 + 256]; r1 = Wv4[i1 + 256];
        __syncthreads();
        #pragma unroll 1
        for (int c = 0; c < 8; c++) {
            float* cur = (c & 1) ? s_m3 : s_wbuf;
            float* nxt = (c & 1) ? s_wbuf : s_m3;
            if (c < 7) {
                ((float4*)nxt)[t] = r0;
                ((float4*)nxt)[t + 512] = r1;
                if (c < 6) {
                    r0 = Wv4[i0 + (c + 2) * 256];
                    r1 = Wv4[i1 + (c + 2) * 256];
                }
            }
            int d0 = c * 16;
            #pragma unroll 2
            for (int d4 = 0; d4 < 4; d4++) {
                float4 xa4 = *(const float4*)(s_se + lane * 132 + d0 + d4 * 4);
                float4 xp4 = *(const float4*)(s_xp + lane * 132 + d0 + d4 * 4);
                float xav[4] = {xa4.x, xa4.y, xa4.z, xa4.w};
                float xpv[4] = {xp4.x, xp4.y, xp4.z, xp4.w};
                #pragma unroll
                for (int dd = 0; dd < 4; dd++) {
                    u64t av2 = bcast2(xav[dd]);
                    u64t pv2 = bcast2(xpv[dd]);
                    int dl = d4 * 4 + dd;
                    const ulonglong2* wvr = (const ulonglong2*)(cur + h * 1024 + dl * 64 + e0);
                    #pragma unroll
                    for (int j = 0; j < 4; j++) {
                        ulonglong2 w2 = wvr[j];
                        aa[2 * j]     = fma2(av2, w2.x, aa[2 * j]);
                        aa[2 * j + 1] = fma2(av2, w2.y, aa[2 * j + 1]);
                        ap[2 * j]     = fma2(pv2, w2.x, ap[2 * j]);
                        ap[2 * j + 1] = fma2(pv2, w2.y, ap[2 * j + 1]);
                    }
                }
            }
            __syncthreads();
        }
        int row = h * 32 + lane;
        #pragma unroll
        for (int j = 0; j < 4; j++) {
            float2 a0 = unpk(aa[2 * j]), a1 = unpk(aa[2 * j + 1]);
            float2 p0 = unpk(ap[2 * j]), p1 = unpk(ap[2 * j + 1]);
            *(float4*)(s_ava + row * 68 + e0 + j * 4) = make_float4(a0.x, a0.y, a1.x, a1.y);
            *(float4*)(s_avp + row * 68 + e0 + j * 4) = make_float4(p0.x, p0.y, p1.x, p1.y);
        }
    }
    __syncthreads();

    // ---------------- P6a: cd = avp - ava ----------------
    #pragma unroll
    for (int g = t; g < 2048; g += 512) {
        int row = g >> 4, e0 = (g & 15) * 4;
        float4 a4 = *(const float4*)(s_ava + row * 68 + e0);
        float4 p4 = *(const float4*)(s_avp + row * 68 + e0);
        *(float4*)(s_cd + row * 68 + e0) =
            make_float4(p4.x - a4.x, p4.y - a4.y, p4.z - a4.z, p4.w - a4.w);
    }
    __syncthreads();

    // ---------------- P6b: cb = w @ ava ----------------
    {
        int h = t >> 7, u = t & 127;
        int i = u >> 2, e0 = (u & 3) * 16;
        u64t acc[8] = {0, 0, 0, 0, 0, 0, 0, 0};
        const float* wrow = s_w + h * 1024 + i * 32;
        const float* av = s_ava + (h * 32) * 68 + e0;
        #pragma unroll 4
        for (int k2 = 0; k2 < 32; k2++) {
            u64t w2 = bcast2(wrow[k2]);
            const ulonglong2* a2 = (const ulonglong2*)(av + k2 * 68);
            ulonglong2 v0 = a2[0], v1 = a2[1], v2 = a2[2], v3 = a2[3];
            acc[0] = fma2(w2, v0.x, acc[0]);
            acc[1] = fma2(w2, v0.y, acc[1]);
            acc[2] = fma2(w2, v1.x, acc[2]);
            acc[3] = fma2(w2, v1.y, acc[3]);
            acc[4] = fma2(w2, v2.x, acc[4]);
            acc[5] = fma2(w2, v2.y, acc[5]);
            acc[6] = fma2(w2, v3.x, acc[6]);
            acc[7] = fma2(w2, v3.y, acc[7]);
        }
        float* cbr = s_cb + (h * 32 + i) * 68 + e0;
        #pragma unroll
        for (int q4 = 0; q4 < 4; q4++) {
            float2 f0 = unpk(acc[q4 * 2]);
            float2 f1 = unpk(acc[q4 * 2 + 1]);
            *(float4*)(cbr + q4 * 4) = make_float4(f0.x, f0.y, f1.x, f1.y);
        }
    }
    __syncthreads();

    // ---------------- P7a: center rows, sbb/sdd ----------------
    if (t < 256) {
        float* row = ((t < 128) ? s_cb : s_cd) + (t & 127) * 68;
        float acc = 0.f;
        #pragma unroll
        for (int e0 = 0; e0 < 64; e0 += 4) {
            float4 v = *(const float4*)(row + e0);
            acc += v.x + v.y + v.z + v.w;
        }
        float mu = acc * (1.f / 64.f);
        float var = 0.f;
        #pragma unroll
        for (int e0 = 0; e0 < 64; e0 += 4) {
            float4 v = *(const float4*)(row + e0);
            v.x -= mu; v.y -= mu; v.z -= mu; v.w -= mu;
            var += v.x * v.x + v.y * v.y + v.z * v.z + v.w * v.w;
            *(float4*)(row + e0) = v;
        }
        var *= (1.f / 64.f);
        if (t < 128) s_sbb[t] = var; else s_sdd[t & 127] = var;
    }
    __syncthreads();

    // ---------------- P7b: sbd[i,j] ----------------
    {
        int h = t >> 7, u = t & 127;
        int i = u >> 2, jg = u & 3;
        u64t acc2[8] = {0, 0, 0, 0, 0, 0, 0, 0};
        const float* cbr = s_cb + (h * 32 + i) * 68;
        const float* cdr = s_cd + (h * 32 + jg * 8) * 68;
        #pragma unroll 2
        for (int e0 = 0; e0 < 64; e0 += 4) {
            ulonglong2 b2 = *(const ulonglong2*)(cbr + e0);
            #pragma unroll
            for (int jj = 0; jj < 8; jj++) {
                ulonglong2 d2 = *(const ulonglong2*)(cdr + jj * 68 + e0);
                acc2[jj] = fma2(b2.x, d2.x, acc2[jj]);
                acc2[jj] = fma2(b2.y, d2.y, acc2[jj]);
            }
        }
        #pragma unroll
        for (int jj = 0; jj < 8; jj++) {
            float2 f = unpk(acc2[jj]);
            s_sbd[h * 1024 + i * 32 + jg * 8 + jj] = (f.x + f.y) * (1.f / 64.f);
        }
    }
    __syncthreads();

    // ---------------- P7c: scale centered cb/cd by ln_g ----------------
    #pragma unroll
    for (int g = t; g < 2048; g += 512) {
        int row = g >> 4, e0 = (g & 15) * 4;
        float4 g4 = *(const float4*)(ln_g + (row >> 5) * 64 + e0);
        float4 b4 = *(const float4*)(s_cb + row * 68 + e0);
        float4 d4 = *(const float4*)(s_cd + row * 68 + e0);
        b4.x *= g4.x; b4.y *= g4.y; b4.z *= g4.z; b4.w *= g4.w;
        d4.x *= g4.x; d4.y *= g4.y; d4.z *= g4.z; d4.w *= g4.w;
        *(float4*)(s_cb + row * 68 + e0) = b4;
        *(float4*)(s_cd + row * 68 + e0) = d4;
    }
    __syncthreads();

    // ---------------- P8: A = cb@W1h, D = cd@W1h ----------------
    {
        int h = t >> 7, u = t & 127;
        int m0 = (u & 15) * 4, nr = u >> 4;
        u64t aA[4][2], aD[4][2];
        #pragma unroll
        for (int r = 0; r < 4; r++) { aA[r][0] = 0; aA[r][1] = 0; aD[r][0] = 0; aD[r][1] = 0; }
        const float* w1b = W_f1 + h * 4096 + m0;
        #pragma unroll 2
        for (int e0 = 0; e0 < 64; e0 += 4) {
            float bvv[4][4], dvv[4][4];
            #pragma unroll
            for (int r = 0; r < 4; r++) {
                int row = h * 32 + nr + 8 * r;
                float4 b4 = *(const float4*)(s_cb + row * 68 + e0);
                float4 d4 = *(const float4*)(s_cd + row * 68 + e0);
                bvv[r][0] = b4.x; bvv[r][1] = b4.y; bvv[r][2] = b4.z; bvv[r][3] = b4.w;
                dvv[r][0] = d4.x; dvv[r][1] = d4.y; dvv[r][2] = d4.z; dvv[r][3] = d4.w;
            }
            #pragma unroll
            for (int ee = 0; ee < 4; ee++) {
                ulonglong2 w2 = *(const ulonglong2*)(w1b + (e0 + ee) * 64);
                #pragma unroll
                for (int r = 0; r < 4; r++) {
                    u64t bv2 = bcast2(bvv[r][ee]);
                    u64t dv2 = bcast2(dvv[r][ee]);
                    aA[r][0] = fma2(bv2, w2.x, aA[r][0]);
                    aA[r][1] = fma2(bv2, w2.y, aA[r][1]);
                    aD[r][0] = fma2(dv2, w2.x, aD[r][0]);
                    aD[r][1] = fma2(dv2, w2.y, aD[r][1]);
                }
            }
        }
        #pragma unroll
        for (int r = 0; r < 4; r++) {
            int row = h * 32 + nr + 8 * r;
            float2 A0 = unpk(aA[r][0]), A1 = unpk(aA[r][1]);
            float2 D0 = unpk(aD[r][0]), D1 = unpk(aD[r][1]);
            *(float4*)(s_A + row * 68 + m0) = make_float4(A0.x, A0.y, A1.x, A1.y);
            *(float4*)(s_D + row * 68 + m0) = make_float4(D0.x, D0.y, D1.x, D1.y);
        }
    }
    __syncthreads();

    // ---------------- P8b: rsq in place of sbd ----------------
    #pragma unroll
    for (int g = t; g < 1024; g += 512) {
        int h = g >> 8, i = (g >> 3) & 31, j0 = (g & 7) * 4;
        int base = h * 1024 + i * 32 + j0;
        float4 w4 = *(const float4*)(s_w + base);
        float4 s4 = *(const float4*)(s_sbd + base);
        float4 dd4 = *(const float4*)(s_sdd + h * 32 + j0);
        float bb = s_sbb[h * 32 + i];
        float4 r;
        r.x = rsqrtf(bb + 2.f * w4.x * s4.x + w4.x * w4.x * dd4.x + 1e-5f);
        r.y = rsqrtf(bb + 2.f * w4.y * s4.y + w4.y * w4.y * dd4.y + 1e-5f);
        r.z = rsqrtf(bb + 2.f * w4.z * s4.z + w4.z * w4.z * dd4.z + 1e-5f);
        r.w = rsqrtf(bb + 2.f * w4.w * s4.w + w4.w * w4.w * dd4.w + 1e-5f);
        *(float4*)(s_sbd + base) = r;
    }
    __syncthreads();

    // ---------------- P9: value (sync-free loop) ----------------
    {
        int j = t >> 4, part = t & 15, m0 = part * 4;
        ulonglong2 C02 = *(const ulonglong2*)(s_C0 + m0);
        float4 W24 = *(const float4*)(s_W2 + m0);
        u64t D2[4][2];
        #pragma unroll
        for (int h = 0; h < 4; h++) {
            ulonglong2 d2 = *(const ulonglong2*)(s_D + (h * 32 + j) * 68 + m0);
            D2[h][0] = d2.x; D2[h][1] = d2.y;
        }
        #pragma unroll 1
        for (int i = 0; i < 32; i++) {
            u64t hid0 = C02.x, hid1 = C02.y;
            #pragma unroll
            for (int h = 0; h < 4; h++) {
                int idx = h * 1024 + i * 32 + j;
                u64t rq2 = bcast2(s_sbd[idx]);
                u64t wv2 = bcast2(s_w[idx]);
                ulonglong2 A2 = *(const ulonglong2*)(s_A + (h * 32 + i) * 68 + m0);
                u64t t0 = fma2(wv2, D2[h][0], A2.x);
                hid0 = fma2(rq2, t0, hid0);
                u64t t1 = fma2(wv2, D2[h][1], A2.y);
                hid1 = fma2(rq2, t1, hid1);
            }
            float2 h0 = unpk(hid0), h1 = unpk(hid1);
            float acc = LEAKY(h0.x) * W24.x + LEAKY(h0.y) * W24.y
                      + LEAKY(h1.x) * W24.z + LEAKY(h1.y) * W24.w;
            acc += __shfl_xor_sync(0xffffffffu, acc, 8);
            acc += __shfl_xor_sync(0xffffffffu, acc, 4);
            acc += __shfl_xor_sync(0xffffffffu, acc, 2);
            acc += __shfl_xor_sync(0xffffffffu, acc, 1);
            if (part == 0) out_v[b * 1024 + i * 32 + j] = acc;
        }
    }
}

extern "C" void kernel_launch(void* const* d_in, const int* in_sizes, int n_in,
                              void* d_out, int out_size) {
    const float* states   = (const float*)d_in[0];
    const float* policies = (const float*)d_in[1];
    const float* actions  = (const float*)d_in[2];
    const float* W_se     = (const float*)d_in[3];
    const float* b_se     = (const float*)d_in[4];
    const float* W_sape   = (const float*)d_in[5];
    const float* b_sape   = (const float*)d_in[6];
    const float* Wk       = (const float*)d_in[7];
    const float* Wq       = (const float*)d_in[8];
    const float* Wv       = (const float*)d_in[9];
    const float* ln_g     = (const float*)d_in[10];
    const float* ln_b     = (const float*)d_in[11];
    const float* W_f1     = (const float*)d_in[12];
    const float* W_f2     = (const float*)d_in[13];

    float* out_v = (float*)d_out;                    // [B,N,N,1]
    float* out_w = (float*)d_out + 128 * 32 * 32;    // [B,H,N,N]

    static int configured = 0;
    if (!configured) {
        cudaFuncSetAttribute(fused_gat_kernel,
                             cudaFuncAttributeMaxDynamicSharedMemorySize, SMEM_BYTES);
        configured = 1;
    }

    fused_gat_kernel<<<128, 512, SMEM_BYTES>>>(states, policies, actions,
                                               W_se, b_se, W_sape, b_sape,
                                               Wk, Wq, Wv, ln_g, ln_b,
                                               W_f1, W_f2, out_v, out_w);
}

// round 16
// speedup vs baseline: 1.1638x; 1.0238x over previous
#include <cuda_runtime.h>

// B=128, N=32, Do=128, Na=16, H=4, Dk=Dv=64, Dio=144
// out: value [B,N,N,1] (131072) then w [B,H,N,N] (524288), fp32

#define LEAKY(x) ((x) > 0.0f ? (x) : 0.01f * (x))

typedef unsigned long long u64t;

__device__ __forceinline__ u64t bcast2(float x) {
    u64t r; asm("mov.b64 %0, {%1, %1};" : "=l"(r) : "f"(x)); return r;
}
__device__ __forceinline__ u64t fma2(u64t a, u64t b, u64t c) {
    u64t d; asm("fma.rn.f32x2 %0, %1, %2, %3;" : "=l"(d) : "l"(a), "l"(b), "l"(c)); return d;
}
__device__ __forceinline__ float2 unpk(u64t v) {
    float2 f; asm("mov.b64 {%0, %1}, %2;" : "=f"(f.x), "=f"(f.y) : "l"(v)); return f;
}

// ---- shared layout (float offsets) ----
#define OFF_W     0        // 4096   softmax w
#define OFF_SBD   4096     // 4096   sbd -> rsq
#define OFF_WBUF  8192     // 4096   staging buf0
#define OFF_ST    12288    // 4224   states row-major [n][132] -> xa after fused phase
#define OFF_ACT   16512    // 640    [n][20]
#define OFF_POL   17152    // 640
#define OFF_SE    17792    // 4224   se row-major [n][132]
#define OFF_XP    22016    // 4224   xp row-major [n][132]
#define OFF_M1    26240    // 8704   q(68) -> ava(68) -> A(68); CP overlay in P0
#define OFF_M2    34944    // 8704   k(68) -> avp(68) -> cb(68)
#define OFF_M3    43648    // 8704   staging buf1 -> cd(68)
#define OFF_SBB   52352    // 128
#define OFF_SDD   52480    // 128
#define OFF_C0    52608    // 64
#define OFF_W2    52672    // 64
#define OFF_D     8192     // 8704   D(68) overlays WBUF+ST+ACT head (dead by P8)
#define SMEM_FLOATS 52736
#define SMEM_BYTES (SMEM_FLOATS * 4)   // 210944 (proven)

__global__ void __launch_bounds__(512, 1)
fused_gat_kernel(const float* __restrict__ states,
                 const float* __restrict__ policies,
                 const float* __restrict__ actions,
                 const float* __restrict__ W_se,
                 const float* __restrict__ b_se,
                 const float* __restrict__ W_sape,
                 const float* __restrict__ b_sape,
                 const float* __restrict__ Wk,
                 const float* __restrict__ Wq,
                 const float* __restrict__ Wv,
                 const float* __restrict__ ln_g,
                 const float* __restrict__ ln_b,
                 const float* __restrict__ W_f1,
                 const float* __restrict__ W_f2,
                 float* __restrict__ out_v,
                 float* __restrict__ out_w)
{
    extern __shared__ float sm[];
    const int t = threadIdx.x;
    const int b = blockIdx.x;
    const int lane = t & 31;
    const int wid = t >> 5;

    float* s_w    = sm + OFF_W;
    float* s_sbd  = sm + OFF_SBD;
    float* s_wbuf = sm + OFF_WBUF;
    float* s_m3   = sm + OFF_M3;
    float* s_st   = sm + OFF_ST;    // states -> xa
    float* s_act  = sm + OFF_ACT;
    float* s_pol  = sm + OFF_POL;
    float* s_se   = sm + OFF_SE;
    float* s_xp   = sm + OFF_XP;
    float* s_q    = sm + OFF_M1;    // stride 68
    float* s_k    = sm + OFF_M2;    // stride 68
    float* s_ava  = sm + OFF_M1;
    float* s_avp  = sm + OFF_M2;
    float* s_cb   = sm + OFF_M2;
    float* s_cd   = sm + OFF_M3;
    float* s_A    = sm + OFF_M1;
    float* s_D    = sm + OFF_D;
    float* s_sbb  = sm + OFF_SBB;
    float* s_sdd  = sm + OFF_SDD;
    float* s_C0   = sm + OFF_C0;
    float* s_W2   = sm + OFF_W2;
    float* s_cp   = sm + OFF_M1;    // CP overlay (P0 only)

    // ---------------- P0: row-major loads + C0 partials ----------------
    {
        #pragma unroll
        for (int o = t; o < 4096; o += 512) {
            int n = o >> 7, d = o & 127;
            s_st[n * 132 + d] = states[b * 4096 + o];
        }
        {
            int n = t >> 4, tt = t & 15;
            s_act[n * 20 + tt] = actions[b * 512 + t];
            s_pol[n * 20 + tt] = policies[b * 512 + t];
        }
        int m = t & 63, fg = t >> 6;
        float acc = 0.f;
        #pragma unroll 8
        for (int f = fg * 32; f < fg * 32 + 32; f++)
            acc += ln_b[f] * W_f1[f * 64 + m];
        s_cp[fg * 64 + m] = acc;
        if (t < 64) s_W2[t] = W_f2[t];
    }
    __syncthreads();
    if (t < 64) {
        float acc = 0.f;
        #pragma unroll
        for (int g2 = 0; g2 < 8; g2++) acc += s_cp[g2 * 64 + t];
        s_C0[t] = acc;
    }

    // ========== P1+P4 fused: se & xa/xp-base from states ==========
    // 8 chunks of 16 d; buffer: [0..2047]=W_se rows, [2048..4095]=W_sape rows
    // warp = 8-col group, lane = n; 8 independent fma2 chains/thread
    {
        int c0 = wid * 8;
        ulonglong2 e0b = *(const ulonglong2*)(b_se + c0);
        ulonglong2 e1b = *(const ulonglong2*)(b_se + c0 + 4);
        ulonglong2 s0b = *(const ulonglong2*)(b_sape + c0);
        ulonglong2 s1b = *(const ulonglong2*)(b_sape + c0 + 4);
        u64t acc[4] = {e0b.x, e0b.y, e1b.x, e1b.y};
        u64t bs[4]  = {s0b.x, s0b.y, s1b.x, s1b.y};
        const float4* Wse4 = (const float4*)W_se;
        const float4* Wsa4 = (const float4*)W_sape;
        float4 pse = Wse4[t], psa = Wsa4[t];
        float4 pft;
        ((float4*)s_wbuf)[t] = pse;
        ((float4*)(s_wbuf + 2048))[t] = psa;
        pse = Wse4[512 + t]; psa = Wsa4[512 + t];
        __syncthreads();
        #pragma unroll 1
        for (int c = 0; c < 8; c++) {
            float* cur = (c & 1) ? s_m3 : s_wbuf;
            float* nxt = (c & 1) ? s_wbuf : s_m3;
            if (c < 7) {
                ((float4*)nxt)[t] = pse;
                ((float4*)(nxt + 2048))[t] = psa;
                if (c < 6) {
                    pse = Wse4[(c + 2) * 512 + t];
                    psa = Wsa4[(c + 2) * 512 + t];
                } else {
                    pft = Wsa4[4096 + t];   // W_sape rows 128..143
                }
            } else {
                ((float4*)nxt)[t] = pft;    // tail into the idle buffer
            }
            int d0 = c * 16;
            #pragma unroll
            for (int d4 = 0; d4 < 4; d4++) {
                float4 a4 = *(const float4*)(s_st + lane * 132 + d0 + d4 * 4);
                float av[4] = {a4.x, a4.y, a4.z, a4.w};
                #pragma unroll
                for (int dd = 0; dd < 4; dd++) {
                    u64t a2 = bcast2(av[dd]);
                    int dl = d4 * 4 + dd;
                    const ulonglong2* we = (const ulonglong2*)(cur + dl * 128 + c0);
                    const ulonglong2* ws = (const ulonglong2*)(cur + 2048 + dl * 128 + c0);
                    ulonglong2 we2a = we[0], we2b = we[1];
                    ulonglong2 ws2a = ws[0], ws2b = ws[1];
                    acc[0] = fma2(a2, we2a.x, acc[0]);
                    acc[1] = fma2(a2, we2a.y, acc[1]);
                    acc[2] = fma2(a2, we2b.x, acc[2]);
                    acc[3] = fma2(a2, we2b.y, acc[3]);
                    bs[0]  = fma2(a2, ws2a.x, bs[0]);
                    bs[1]  = fma2(a2, ws2a.y, bs[1]);
                    bs[2]  = fma2(a2, ws2b.x, bs[2]);
                    bs[3]  = fma2(a2, ws2b.y, bs[3]);
                }
            }
            __syncthreads();
        }
        // se ready — write it now (c0 cols of row 'lane')
        #pragma unroll
        for (int k = 0; k < 4; k++) {
            float2 f = unpk(acc[k]);
            s_se[lane * 132 + c0 + 2 * k]     = LEAKY(f.x);
            s_se[lane * 132 + c0 + 2 * k + 1] = LEAKY(f.y);
        }
        // tail: action/policy rows 128..143; weights staged in the buffer
        // written during c==7 (nxt of c=7 is WBUF)
        u64t aa[4], ap[4];
        #pragma unroll
        for (int k = 0; k < 4; k++) { aa[k] = bs[k]; ap[k] = bs[k]; }
        #pragma unroll
        for (int t4 = 0; t4 < 4; t4++) {
            float4 sa4 = *(const float4*)(s_act + lane * 20 + t4 * 4);
            float4 sp4 = *(const float4*)(s_pol + lane * 20 + t4 * 4);
            float sav[4] = {sa4.x, sa4.y, sa4.z, sa4.w};
            float spv[4] = {sp4.x, sp4.y, sp4.z, sp4.w};
            #pragma unroll
            for (int dd = 0; dd < 4; dd++) {
                int tt = t4 * 4 + dd;
                u64t av = bcast2(sav[dd]);
                u64t pv = bcast2(spv[dd]);
                const ulonglong2* wr = (const ulonglong2*)(s_wbuf + tt * 128 + c0);
                ulonglong2 w0 = wr[0], w1 = wr[1];
                aa[0] = fma2(av, w0.x, aa[0]);
                aa[1] = fma2(av, w0.y, aa[1]);
                aa[2] = fma2(av, w1.x, aa[2]);
                aa[3] = fma2(av, w1.y, aa[3]);
                ap[0] = fma2(pv, w0.x, ap[0]);
                ap[1] = fma2(pv, w0.y, ap[1]);
                ap[2] = fma2(pv, w1.x, ap[2]);
                ap[3] = fma2(pv, w1.y, ap[3]);
            }
        }
        // xa overwrites states (all main-loop reads of s_st completed at the
        // final chunk barrier; tail reads only act/pol/WBUF)
        #pragma unroll
        for (int k = 0; k < 4; k++) {
            float2 fa = unpk(aa[k]), fp = unpk(ap[k]);
            s_st[lane * 132 + c0 + 2 * k]     = LEAKY(fa.x);   // xa
            s_st[lane * 132 + c0 + 2 * k + 1] = LEAKY(fa.y);
            s_xp[lane * 132 + c0 + 2 * k]     = LEAKY(fp.x);
            s_xp[lane * 132 + c0 + 2 * k + 1] = LEAKY(fp.y);
        }
    }
    __syncthreads();   // se/xa/xp visible; WBUF tail reads done before P2 staging

    // ---------------- P2: q,k = se @ Wq / se @ Wk (fused staging) --------
    // warp = (h = wid>>2, e0 = (wid&3)*16), lane = n; 16 chunks of 8d
    {
        int h = wid >> 2, e0 = (wid & 3) * 16;
        u64t aq[8], ak[8];
        #pragma unroll
        for (int k = 0; k < 8; k++) { aq[k] = 0; ak[k] = 0; }
        int hh = t >> 7, rem = t & 127;
        int sidx = hh * 2048 + (rem >> 4) * 16 + (rem & 15);
        const float4* Wq4 = (const float4*)Wq;
        const float4* Wk4 = (const float4*)Wk;
        float4 pq = Wq4[sidx], pk = Wk4[sidx];
        ((float4*)s_wbuf)[t] = pq;
        ((float4*)s_wbuf)[t + 512] = pk;
        pq = Wq4[sidx + 128]; pk = Wk4[sidx + 128];
        __syncthreads();
        #pragma unroll 1
        for (int c = 0; c < 16; c++) {
            float* cur = (c & 1) ? s_m3 : s_wbuf;
            float* nxt = (c & 1) ? s_wbuf : s_m3;
            if (c < 15) {
                ((float4*)nxt)[t] = pq;
                ((float4*)nxt)[t + 512] = pk;
                if (c < 14) {
                    pq = Wq4[sidx + (c + 2) * 128];
                    pk = Wk4[sidx + (c + 2) * 128];
                }
            }
            int d0 = c * 8;
            #pragma unroll
            for (int d4 = 0; d4 < 2; d4++) {
                float4 a4 = *(const float4*)(s_se + lane * 132 + d0 + d4 * 4);
                float av[4] = {a4.x, a4.y, a4.z, a4.w};
                #pragma unroll
                for (int dd = 0; dd < 4; dd++) {
                    u64t a2 = bcast2(av[dd]);
                    int dl = d4 * 4 + dd;
                    const ulonglong2* wqr = (const ulonglong2*)(cur + h * 512 + dl * 64 + e0);
                    const ulonglong2* wkr = (const ulonglong2*)(cur + 2048 + h * 512 + dl * 64 + e0);
                    #pragma unroll
                    for (int j = 0; j < 4; j++) {
                        ulonglong2 wq2 = wqr[j];
                        ulonglong2 wk2 = wkr[j];
                        aq[2 * j]     = fma2(a2, wq2.x, aq[2 * j]);
                        aq[2 * j + 1] = fma2(a2, wq2.y, aq[2 * j + 1]);
                        ak[2 * j]     = fma2(a2, wk2.x, ak[2 * j]);
                        ak[2 * j + 1] = fma2(a2, wk2.y, ak[2 * j + 1]);
                    }
                }
            }
            __syncthreads();
        }
        int row = h * 32 + lane;
        #pragma unroll
        for (int j = 0; j < 4; j++) {
            float2 q0 = unpk(aq[2 * j]), q1 = unpk(aq[2 * j + 1]);
            float2 k0 = unpk(ak[2 * j]), k1 = unpk(ak[2 * j + 1]);
            *(float4*)(s_q + row * 68 + e0 + j * 4) = make_float4(q0.x, q0.y, q1.x, q1.y);
            *(float4*)(s_k + row * 68 + e0 + j * 4) = make_float4(k0.x, k0.y, k1.x, k1.y);
        }
    }
    __syncthreads();

    // ---------------- P3: scores ----------------
    {
        int h = t >> 7, rem = t & 127;
        int i = rem >> 2, k2g = rem & 3;
        u64t acc2[8] = {0, 0, 0, 0, 0, 0, 0, 0};
        const float* qr = s_q + (h * 32 + i) * 68;
        const float* kb = s_k + (h * 32 + k2g * 8) * 68;
        #pragma unroll 2
        for (int e0 = 0; e0 < 64; e0 += 4) {
            ulonglong2 q2 = *(const ulonglong2*)(qr + e0);
            #pragma unroll
            for (int kk = 0; kk < 8; kk++) {
                ulonglong2 k2v = *(const ulonglong2*)(kb + kk * 68 + e0);
                acc2[kk] = fma2(q2.x, k2v.x, acc2[kk]);
                acc2[kk] = fma2(q2.y, k2v.y, acc2[kk]);
            }
        }
        #pragma unroll
        for (int kk = 0; kk < 8; kk++) {
            float2 f = unpk(acc2[kk]);
            s_w[h * 1024 + i * 32 + k2g * 8 + kk] = (f.x + f.y) * 0.125f;
        }
    }
    __syncthreads();

    // ---------------- softmax ----------------
    if (t < 128) {
        float* row = s_w + t * 32;
        float mx = row[0];
        #pragma unroll
        for (int j = 1; j < 32; j++) mx = fmaxf(mx, row[j]);
        float s = 0.f;
        #pragma unroll
        for (int j = 0; j < 32; j++) { float ex = __expf(row[j] - mx); row[j] = ex; s += ex; }
        float inv = 1.f / s;
        #pragma unroll
        for (int j = 0; j < 32; j++) row[j] *= inv;
    }
    __syncthreads();
    #pragma unroll
    for (int g = t; g < 1024; g += 512)
        *(float4*)(out_w + b * 4096 + g * 4) = *(const float4*)(s_w + g * 4);

    // ---------------- P5: ava/avp = xa/xp @ Wv (8 chunks of 16d) ---------
    {
        int h = wid >> 2, e0 = (wid & 3) * 16;
        u64t aa[8], ap[8];
        #pragma unroll
        for (int k = 0; k < 8; k++) { aa[k] = 0; ap[k] = 0; }
        int g1 = t + 512;
        int i0 = (t >> 8) * 2048 + ((t & 255) >> 4) * 16 + (t & 15);
        int i1 = (g1 >> 8) * 2048 + ((g1 & 255) >> 4) * 16 + (g1 & 15);
        const float4* Wv4 = (const float4*)Wv;
        float4 r0 = Wv4[i0], r1 = Wv4[i1];
        ((float4*)s_wbuf)[t] = r0;
        ((float4*)s_wbuf)[t + 512] = r1;
        r0 = Wv4[i0 + 256]; r1 = Wv4[i1 + 256];
        __syncthreads();
        #pragma unroll 1
        for (int c = 0; c < 8; c++) {
            float* cur = (c & 1) ? s_m3 : s_wbuf;
            float* nxt = (c & 1) ? s_wbuf : s_m3;
            if (c < 7) {
                ((float4*)nxt)[t] = r0;
                ((float4*)nxt)[t + 512] = r1;
                if (c < 6) {
                    r0 = Wv4[i0 + (c + 2) * 256];
                    r1 = Wv4[i1 + (c + 2) * 256];
                }
            }
            int d0 = c * 16;
            #pragma unroll 2
            for (int d4 = 0; d4 < 4; d4++) {
                float4 xa4 = *(const float4*)(s_st + lane * 132 + d0 + d4 * 4);   // xa
                float4 xp4 = *(const float4*)(s_xp + lane * 132 + d0 + d4 * 4);
                float xav[4] = {xa4.x, xa4.y, xa4.z, xa4.w};
                float xpv[4] = {xp4.x, xp4.y, xp4.z, xp4.w};
                #pragma unroll
                for (int dd = 0; dd < 4; dd++) {
                    u64t av2 = bcast2(xav[dd]);
                    u64t pv2 = bcast2(xpv[dd]);
                    int dl = d4 * 4 + dd;
                    const ulonglong2* wvr = (const ulonglong2*)(cur + h * 1024 + dl * 64 + e0);
                    #pragma unroll
                    for (int j = 0; j < 4; j++) {
                        ulonglong2 w2 = wvr[j];
                        aa[2 * j]     = fma2(av2, w2.x, aa[2 * j]);
                        aa[2 * j + 1] = fma2(av2, w2.y, aa[2 * j + 1]);
                        ap[2 * j]     = fma2(pv2, w2.x, ap[2 * j]);
                        ap[2 * j + 1] = fma2(pv2, w2.y, ap[2 * j + 1]);
                    }
                }
            }
            __syncthreads();
        }
        int row = h * 32 + lane;
        #pragma unroll
        for (int j = 0; j < 4; j++) {
            float2 a0 = unpk(aa[2 * j]), a1 = unpk(aa[2 * j + 1]);
            float2 p0 = unpk(ap[2 * j]), p1 = unpk(ap[2 * j + 1]);
            *(float4*)(s_ava + row * 68 + e0 + j * 4) = make_float4(a0.x, a0.y, a1.x, a1.y);
            *(float4*)(s_avp + row * 68 + e0 + j * 4) = make_float4(p0.x, p0.y, p1.x, p1.y);
        }
    }
    __syncthreads();

    // ---------------- P6a: cd = avp - ava ----------------
    #pragma unroll
    for (int g = t; g < 2048; g += 512) {
        int row = g >> 4, e0 = (g & 15) * 4;
        float4 a4 = *(const float4*)(s_ava + row * 68 + e0);
        float4 p4 = *(const float4*)(s_avp + row * 68 + e0);
        *(float4*)(s_cd + row * 68 + e0) =
            make_float4(p4.x - a4.x, p4.y - a4.y, p4.z - a4.z, p4.w - a4.w);
    }
    __syncthreads();

    // ---------------- P6b: cb = w @ ava ----------------
    {
        int h = t >> 7, u = t & 127;
        int i = u >> 2, e0 = (u & 3) * 16;
        u64t acc[8] = {0, 0, 0, 0, 0, 0, 0, 0};
        const float* wrow = s_w + h * 1024 + i * 32;
        const float* av = s_ava + (h * 32) * 68 + e0;
        #pragma unroll 4
        for (int k2 = 0; k2 < 32; k2++) {
            u64t w2 = bcast2(wrow[k2]);
            const ulonglong2* a2 = (const ulonglong2*)(av + k2 * 68);
            ulonglong2 v0 = a2[0], v1 = a2[1], v2 = a2[2], v3 = a2[3];
            acc[0] = fma2(w2, v0.x, acc[0]);
            acc[1] = fma2(w2, v0.y, acc[1]);
            acc[2] = fma2(w2, v1.x, acc[2]);
            acc[3] = fma2(w2, v1.y, acc[3]);
            acc[4] = fma2(w2, v2.x, acc[4]);
            acc[5] = fma2(w2, v2.y, acc[5]);
            acc[6] = fma2(w2, v3.x, acc[6]);
            acc[7] = fma2(w2, v3.y, acc[7]);
        }
        float* cbr = s_cb + (h * 32 + i) * 68 + e0;
        #pragma unroll
        for (int q4 = 0; q4 < 4; q4++) {
            float2 f0 = unpk(acc[q4 * 2]);
            float2 f1 = unpk(acc[q4 * 2 + 1]);
            *(float4*)(cbr + q4 * 4) = make_float4(f0.x, f0.y, f1.x, f1.y);
        }
    }
    __syncthreads();

    // ---------------- P7a: center rows, sbb/sdd ----------------
    if (t < 256) {
        float* row = ((t < 128) ? s_cb : s_cd) + (t & 127) * 68;
        float acc = 0.f;
        #pragma unroll
        for (int e0 = 0; e0 < 64; e0 += 4) {
            float4 v = *(const float4*)(row + e0);
            acc += v.x + v.y + v.z + v.w;
        }
        float mu = acc * (1.f / 64.f);
        float var = 0.f;
        #pragma unroll
        for (int e0 = 0; e0 < 64; e0 += 4) {
            float4 v = *(const float4*)(row + e0);
            v.x -= mu; v.y -= mu; v.z -= mu; v.w -= mu;
            var += v.x * v.x + v.y * v.y + v.z * v.z + v.w * v.w;
            *(float4*)(row + e0) = v;
        }
        var *= (1.f / 64.f);
        if (t < 128) s_sbb[t] = var; else s_sdd[t & 127] = var;
    }
    __syncthreads();

    // ---------------- P7b: sbd[i,j] ----------------
    {
        int h = t >> 7, u = t & 127;
        int i = u >> 2, jg = u & 3;
        u64t acc2[8] = {0, 0, 0, 0, 0, 0, 0, 0};
        const float* cbr = s_cb + (h * 32 + i) * 68;
        const float* cdr = s_cd + (h * 32 + jg * 8) * 68;
        #pragma unroll 2
        for (int e0 = 0; e0 < 64; e0 += 4) {
            ulonglong2 b2 = *(const ulonglong2*)(cbr + e0);
            #pragma unroll
            for (int jj = 0; jj < 8; jj++) {
                ulonglong2 d2 = *(const ulonglong2*)(cdr + jj * 68 + e0);
                acc2[jj] = fma2(b2.x, d2.x, acc2[jj]);
                acc2[jj] = fma2(b2.y, d2.y, acc2[jj]);
            }
        }
        #pragma unroll
        for (int jj = 0; jj < 8; jj++) {
            float2 f = unpk(acc2[jj]);
            s_sbd[h * 1024 + i * 32 + jg * 8 + jj] = (f.x + f.y) * (1.f / 64.f);
        }
    }
    __syncthreads();

    // ---------------- P7c: scale centered cb/cd by ln_g ----------------
    #pragma unroll
    for (int g = t; g < 2048; g += 512) {
        int row = g >> 4, e0 = (g & 15) * 4;
        float4 g4 = *(const float4*)(ln_g + (row >> 5) * 64 + e0);
        float4 b4 = *(const float4*)(s_cb + row * 68 + e0);
        float4 d4 = *(const float4*)(s_cd + row * 68 + e0);
        b4.x *= g4.x; b4.y *= g4.y; b4.z *= g4.z; b4.w *= g4.w;
        d4.x *= g4.x; d4.y *= g4.y; d4.z *= g4.z; d4.w *= g4.w;
        *(float4*)(s_cb + row * 68 + e0) = b4;
        *(float4*)(s_cd + row * 68 + e0) = d4;
    }
    __syncthreads();

    // ---------------- P8: A = cb@W1h, D = cd@W1h ----------------
    {
        int h = t >> 7, u = t & 127;
        int m0 = (u & 15) * 4, nr = u >> 4;
        u64t aA[4][2], aD[4][2];
        #pragma unroll
        for (int r = 0; r < 4; r++) { aA[r][0] = 0; aA[r][1] = 0; aD[r][0] = 0; aD[r][1] = 0; }
        const float* w1b = W_f1 + h * 4096 + m0;
        #pragma unroll 2
        for (int e0 = 0; e0 < 64; e0 += 4) {
            float bvv[4][4], dvv[4][4];
            #pragma unroll
            for (int r = 0; r < 4; r++) {
                int row = h * 32 + nr + 8 * r;
                float4 b4 = *(const float4*)(s_cb + row * 68 + e0);
                float4 d4 = *(const float4*)(s_cd + row * 68 + e0);
                bvv[r][0] = b4.x; bvv[r][1] = b4.y; bvv[r][2] = b4.z; bvv[r][3] = b4.w;
                dvv[r][0] = d4.x; dvv[r][1] = d4.y; dvv[r][2] = d4.z; dvv[r][3] = d4.w;
            }
            #pragma unroll
            for (int ee = 0; ee < 4; ee++) {
                ulonglong2 w2 = *(const ulonglong2*)(w1b + (e0 + ee) * 64);
                #pragma unroll
                for (int r = 0; r < 4; r++) {
                    u64t bv2 = bcast2(bvv[r][ee]);
                    u64t dv2 = bcast2(dvv[r][ee]);
                    aA[r][0] = fma2(bv2, w2.x, aA[r][0]);
                    aA[r][1] = fma2(bv2, w2.y, aA[r][1]);
                    aD[r][0] = fma2(dv2, w2.x, aD[r][0]);
                    aD[r][1] = fma2(dv2, w2.y, aD[r][1]);
                }
            }
        }
        #pragma unroll
        for (int r = 0; r < 4; r++) {
            int row = h * 32 + nr + 8 * r;
            float2 A0 = unpk(aA[r][0]), A1 = unpk(aA[r][1]);
            float2 D0 = unpk(aD[r][0]), D1 = unpk(aD[r][1]);
            *(float4*)(s_A + row * 68 + m0) = make_float4(A0.x, A0.y, A1.x, A1.y);
            *(float4*)(s_D + row * 68 + m0) = make_float4(D0.x, D0.y, D1.x, D1.y);
        }
    }
    __syncthreads();

    // ---------------- P8b: rsq in place of sbd ----------------
    #pragma unroll
    for (int g = t; g < 1024; g += 512) {
        int h = g >> 8, i = (g >> 3) & 31, j0 = (g & 7) * 4;
        int base = h * 1024 + i * 32 + j0;
        float4 w4 = *(const float4*)(s_w + base);
        float4 s4 = *(const float4*)(s_sbd + base);
        float4 dd4 = *(const float4*)(s_sdd + h * 32 + j0);
        float bb = s_sbb[h * 32 + i];
        float4 r;
        r.x = rsqrtf(bb + 2.f * w4.x * s4.x + w4.x * w4.x * dd4.x + 1e-5f);
        r.y = rsqrtf(bb + 2.f * w4.y * s4.y + w4.y * w4.y * dd4.y + 1e-5f);
        r.z = rsqrtf(bb + 2.f * w4.z * s4.z + w4.z * w4.z * dd4.z + 1e-5f);
        r.w = rsqrtf(bb + 2.f * w4.w * s4.w + w4.w * w4.w * dd4.w + 1e-5f);
        *(float4*)(s_sbd + base) = r;
    }
    __syncthreads();

    // ---------------- P9: value (sync-free, unroll 2 for shfl overlap) ---
    {
        int j = t >> 4, part = t & 15, m0 = part * 4;
        ulonglong2 C02 = *(const ulonglong2*)(s_C0 + m0);
        float4 W24 = *(const float4*)(s_W2 + m0);
        u64t D2[4][2];
        #pragma unroll
        for (int h = 0; h < 4; h++) {
            ulonglong2 d2 = *(const ulonglong2*)(s_D + (h * 32 + j) * 68 + m0);
            D2[h][0] = d2.x; D2[h][1] = d2.y;
        }
        #pragma unroll 2
        for (int i = 0; i < 32; i++) {
            u64t hid0 = C02.x, hid1 = C02.y;
            #pragma unroll
            for (int h = 0; h < 4; h++) {
                int idx = h * 1024 + i * 32 + j;
                u64t rq2 = bcast2(s_sbd[idx]);
                u64t wv2 = bcast2(s_w[idx]);
                ulonglong2 A2 = *(const ulonglong2*)(s_A + (h * 32 + i) * 68 + m0);
                u64t t0 = fma2(wv2, D2[h][0], A2.x);
                hid0 = fma2(rq2, t0, hid0);
                u64t t1 = fma2(wv2, D2[h][1], A2.y);
                hid1 = fma2(rq2, t1, hid1);
            }
            float2 h0 = unpk(hid0), h1 = unpk(hid1);
            float acc = LEAKY(h0.x) * W24.x + LEAKY(h0.y) * W24.y
                      + LEAKY(h1.x) * W24.z + LEAKY(h1.y) * W24.w;
            acc += __shfl_xor_sync(0xffffffffu, acc, 8);
            acc += __shfl_xor_sync(0xffffffffu, acc, 4);
            acc += __shfl_xor_sync(0xffffffffu, acc, 2);
            acc += __shfl_xor_sync(0xffffffffu, acc, 1);
            if (part == 0) out_v[b * 1024 + i * 32 + j] = acc;
        }
    }
}

extern "C" void kernel_launch(void* const* d_in, const int* in_sizes, int n_in,
                              void* d_out, int out_size) {
    const float* states   = (const float*)d_in[0];
    const float* policies = (const float*)d_in[1];
    const float* actions  = (const float*)d_in[2];
    const float* W_se     = (const float*)d_in[3];
    const float* b_se     = (const float*)d_in[4];
    const float* W_sape   = (const float*)d_in[5];
    const float* b_sape   = (const float*)d_in[6];
    const float* Wk       = (const float*)d_in[7];
    const float* Wq       = (const float*)d_in[8];
    const float* Wv       = (const float*)d_in[9];
    const float* ln_g     = (const float*)d_in[10];
    const float* ln_b     = (const float*)d_in[11];
    const float* W_f1     = (const float*)d_in[12];
    const float* W_f2     = (const float*)d_in[13];

    float* out_v = (float*)d_out;                    // [B,N,N,1]
    float* out_w = (float*)d_out + 128 * 32 * 32;    // [B,H,N,N]

    static int configured = 0;
    if (!configured) {
        cudaFuncSetAttribute(fused_gat_kernel,
                             cudaFuncAttributeMaxDynamicSharedMemorySize, SMEM_BYTES);
        configured = 1;
    }

    fused_gat_kernel<<<128, 512, SMEM_BYTES>>>(states, policies, actions,
                                               W_se, b_se, W_sape, b_sape,
                                               Wk, Wq, Wv, ln_g, ln_b,
                                               W_f1, W_f2, out_v, out_w);
}